// round 5
// baseline (speedup 1.0000x reference)
#include <cuda_runtime.h>
#include <cuda_bf16.h>

// ---------------- problem constants ----------------
#define B_    64
#define L_    512
#define G_    128
#define N_    32
#define K_    8
#define E_    65536
#define DTOK  64
#define H_    64
#define NINP  32
#define NRH   256          // NREL*NHID = 16*16
#define NA    2048         // B*N

typedef unsigned long long u64;

// ---------------- scratch (__device__ globals; no allocation) ----------------
__device__ float g_xgrp[B_*G_*DTOK];        // (B,G,64)
__device__ float g_gx[128*G_*256];          // (bid, t, gate) 16.7MB
__device__ float g_hgrp[B_*G_*2*H_];        // (B,G,128)  fwd[0:64) bwd[64:128)
__device__ float g_rawS[NA*NINP];
__device__ float g_rawD[NA*NINP];
__device__ float g_hsT [NA*NINP];
__device__ float g_htT [NA*NINP];
__device__ int   g_cntU[NA];
__device__ int   g_cntV[NA];
__device__ int   g_start[NA+1];
__device__ int   g_cursor[NA];
__device__ int   g_perm[E_];
__device__ float g_bnMu[64];
__device__ float g_bnInv[64];
__device__ float g_Ap[(size_t)NA*NRH*32];   // 64 MB
__device__ float g_C [NA*NRH];
__device__ float g_zsum[NRH];
__device__ float g_zsq [NRH];
__device__ float g_zscale[NRH];
__device__ float g_zoff  [NRH];

// ---------------- math helpers ----------------
__device__ __forceinline__ float tanha(float x) {           // MUFU.TANH
    float y; asm("tanh.approx.f32 %0, %1;" : "=f"(y) : "f"(x)); return y;
}
__device__ __forceinline__ float siga(float x) {            // exact identity
    return fmaf(0.5f, tanha(0.5f * x), 0.5f);
}
__device__ __forceinline__ u64 ffma2(u64 a, u64 b, u64 c) { // packed f32x2 FMA
    u64 d; asm("fma.rn.f32x2 %0, %1, %2, %3;" : "=l"(d) : "l"(a), "l"(b), "l"(c));
    return d;
}
__device__ __forceinline__ float hsum2(u64 x) {
    return __uint_as_float((unsigned)(x & 0xffffffffull)) +
           __uint_as_float((unsigned)(x >> 32));
}
__device__ __forceinline__ void nbar(int id) {              // named barrier, 256 thr
    asm volatile("bar.sync %0, %1;" :: "r"(id), "r"(256) : "memory");
}

// ---------------- 1: zero counters ----------------
__global__ void k_init() {
    int t = blockIdx.x * 256 + threadIdx.x;
    if (t < NA)  { g_cntU[t] = 0; g_cntV[t] = 0; }
    if (t < NRH) { g_zsum[t] = 0.f; g_zsq[t] = 0.f; }
}

// ---------------- 2: token embed + scatter-sum into groups (one CTA per b) ----
__global__ void k_embed(const int* __restrict__ seq, const int* __restrict__ p2g,
                        const float* __restrict__ emb) {
    __shared__ float acc[G_ * DTOK];          // 32 KB
    int b = blockIdx.x;
    int tid = threadIdx.x;                    // 256
    for (int i = tid; i < G_ * DTOK; i += 256) acc[i] = 0.f;
    __syncthreads();
    int sub  = tid & 15;                      // 16 threads per token (float4 each)
    int tok0 = tid >> 4;
    for (int l = tok0; l < L_; l += 16) {
        int s = seq[b * L_ + l];
        int g = p2g[b * L_ + l];
        float4 v = ((const float4*)(emb + (size_t)s * DTOK))[sub];
        float* dst = acc + g * DTOK + sub * 4;
        atomicAdd(dst + 0, v.x); atomicAdd(dst + 1, v.y);
        atomicAdd(dst + 2, v.z); atomicAdd(dst + 3, v.w);
    }
    __syncthreads();
    for (int i = tid; i < G_ * DTOK; i += 256) g_xgrp[b * G_ * DTOK + i] = acc[i];
}

// ---------------- 3: edge-endpoint histograms ----------------
__global__ void k_histo(const int* __restrict__ u, const int* __restrict__ v) {
    int e = blockIdx.x * 256 + threadIdx.x;
    atomicAdd(&g_cntU[u[e]], 1);
    atomicAdd(&g_cntV[v[e]], 1);
}

// ---------------- 4a: input projection gx[bid][t][gate], 256 CTAs -----------
__global__ void __launch_bounds__(256)
k_xproj(const float* __restrict__ wihF, const float* __restrict__ bihF,
        const float* __restrict__ bhhF,
        const float* __restrict__ wihB, const float* __restrict__ bihB,
        const float* __restrict__ bhhB) {
    int cta = blockIdx.x;                     // 0..255
    int bid = cta >> 1;                       // 0..127
    int tp  = cta & 1;                        // t-half
    int b   = bid & 63;
    int dir = bid >> 6;
    const float* wih = dir ? wihB : wihF;
    const float* bih = dir ? bihB : bihF;
    const float* bhh = dir ? bhhB : bhhF;
    int j = threadIdx.x;                      // gate row

    int tbeg   = tp * 64;
    int tgbase = dir ? (64 - tbeg) : tbeg;    // contiguous 64-group window

    __shared__ u64 xsm[64 * DTOK / 2];        // 16 KB
    const u64* src = (const u64*)(g_xgrp + (b * G_ + tgbase) * DTOK);
    #pragma unroll
    for (int i = 0; i < 8; i++) xsm[j + i * 256] = src[j + i * 256];

    u64 wi2[32];
    const u64* wip = (const u64*)(wih + j * DTOK);
    #pragma unroll
    for (int k = 0; k < 32; k++) wi2[k] = wip[k];
    float bias = bih[j] + bhh[j];
    __syncthreads();

    float* dst = g_gx + (size_t)bid * G_ * 256 + j;
    #pragma unroll 2
    for (int tt = 0; tt < 64; tt++) {
        int t  = tbeg + tt;
        int tg = dir ? (G_ - 1 - t) : t;
        const u64* xp = xsm + (tg - tgbase) * 32;
        u64 a0 = 0, a1 = 0, a2 = 0, a3 = 0;
        #pragma unroll
        for (int k = 0; k < 32; k += 4) {
            a0 = ffma2(wi2[k+0], xp[k+0], a0);
            a1 = ffma2(wi2[k+1], xp[k+1], a1);
            a2 = ffma2(wi2[k+2], xp[k+2], a2);
            a3 = ffma2(wi2[k+3], xp[k+3], a3);
        }
        dst[t * 256] = bias + (hsum2(a0) + hsum2(a1)) + (hsum2(a2) + hsum2(a3));
    }
}

// ---------------- 4b: recurrence, 2 sequences per CTA, named barriers -------
__global__ void __launch_bounds__(512, 1)
k_lstm(const float* __restrict__ whhF, const float* __restrict__ whhB) {
    int tid  = threadIdx.x;
    int half = tid >> 8;                      // sequence slot 0/1
    int j    = tid & 255;                     // gate row
    int bid  = blockIdx.x * 2 + half;         // 0..127
    int b    = bid & 63;
    int dir  = bid >> 6;
    const float* whh = dir ? whhB : whhF;
    int barid = half + 1;

    u64 wh2[32];
    const u64* whp = (const u64*)(whh + j * H_);
    #pragma unroll
    for (int k = 0; k < 32; k++) wh2[k] = whp[k];

    __shared__ u64 hsm[2][32];                 // current h per sequence
    __shared__ float gsm[2][256];              // activated gates per sequence
    float c = 0.f;
    if (j < 32) hsm[half][j] = 0ull;

    const float* gx = g_gx + (size_t)bid * G_ * 256 + j;
    int gate = j >> 6;                         // 0:i 1:f 2:g 3:o
    nbar(barid);
    float gxr = gx[0];

    for (int t = 0; t < G_; t++) {
        float gxn = gx[(t + 1 < G_ ? t + 1 : t) * 256];   // prefetch
        const u64* hp = hsm[half];
        u64 a0 = 0, a1 = 0, a2 = 0, a3 = 0;
        #pragma unroll
        for (int k = 0; k < 32; k += 4) {
            a0 = ffma2(wh2[k+0], hp[k+0], a0);
            a1 = ffma2(wh2[k+1], hp[k+1], a1);
            a2 = ffma2(wh2[k+2], hp[k+2], a2);
            a3 = ffma2(wh2[k+3], hp[k+3], a3);
        }
        float pre = gxr + (hsum2(a0) + hsum2(a1)) + (hsum2(a2) + hsum2(a3));
        // activation applied pre-barrier, off the serial path
        gsm[half][j] = (gate == 2) ? tanha(pre) : siga(pre);
        gxr = gxn;
        nbar(barid);
        if (j < 64) {
            float ai = gsm[half][j],       af = gsm[half][64 + j];
            float ag = gsm[half][128 + j], ao = gsm[half][192 + j];
            c = fmaf(af, c, ai * ag);
            float h = ao * tanha(c);
            ((float*)hsm[half])[j] = h;
            int tg = dir ? (G_ - 1 - t) : t;
            g_hgrp[(b * G_ + tg) * (2 * H_) + dir * H_ + j] = h;
        }
        nbar(barid);
    }
}

// ---------------- 5: node gather (sum K groups) + endpoint projections -------
__global__ void k_nodeproj(const int* __restrict__ p2g, const int* __restrict__ idx,
                           const float* __restrict__ wS, const float* __restrict__ bS,
                           const float* __restrict__ wD, const float* __restrict__ bD) {
    int a = blockIdx.x;                       // node 0..2047
    int b = a >> 5, n = a & 31;
    int tid = threadIdx.x;                    // 64
    __shared__ float4 hrow4[32];              // 128 floats
    float* hrow = (float*)hrow4;
    float s0 = 0.f, s1 = 0.f;
    #pragma unroll
    for (int k = 0; k < K_; k++) {
        int pos = idx[(b * N_ + n) * K_ + k];
        int g   = p2g[b * L_ + pos];
        const float* hp = g_hgrp + (b * G_ + g) * (2 * H_);
        s0 += hp[tid]; s1 += hp[tid + 64];
    }
    hrow[tid] = s0; hrow[tid + 64] = s1;
    __syncthreads();
    const float* w = (tid < 32) ? (wS + tid * 128) : (wD + (tid - 32) * 128);
    float bb = (tid < 32) ? bS[tid] : bD[tid - 32];
    const u64* h2 = (const u64*)hrow;
    const u64* w2 = (const u64*)w;
    u64 a0 = 0, a1 = 0, a2 = 0, a3 = 0;
    #pragma unroll
    for (int q = 0; q < 64; q += 4) {
        a0 = ffma2(w2[q+0], h2[q+0], a0);
        a1 = ffma2(w2[q+1], h2[q+1], a1);
        a2 = ffma2(w2[q+2], h2[q+2], a2);
        a3 = ffma2(w2[q+3], h2[q+3], a3);
    }
    float acc = bb + (hsum2(a0) + hsum2(a1)) + (hsum2(a2) + hsum2(a3));
    if (tid < 32) g_rawS[a * NINP + tid] = acc;
    else          g_rawD[a * NINP + tid - 32] = acc;
}

// ---------------- 6: BN stats as count-weighted moments (exact) --------------
__global__ void k_bnstats() {
    int c = blockIdx.x;                       // 0..63 (src 0-31, dst 32-63)
    int tid = threadIdx.x;
    const float* raw = (c < 32) ? g_rawS : g_rawD;
    const int*   cnt = (c < 32) ? g_cntU : g_cntV;
    int cc = c & 31;
    float s = 0.f, s2 = 0.f;
    for (int a = tid; a < NA; a += 256) {
        float w = (float)cnt[a];
        float x = raw[a * NINP + cc];
        s += w * x; s2 += w * x * x;
    }
    __shared__ float r1[256], r2[256];
    r1[tid] = s; r2[tid] = s2; __syncthreads();
    for (int o = 128; o > 0; o >>= 1) {
        if (tid < o) { r1[tid] += r1[tid + o]; r2[tid] += r2[tid + o]; }
        __syncthreads();
    }
    if (tid == 0) {
        float mu  = r1[0] * (1.0f / E_);
        float var = r2[0] * (1.0f / E_) - mu * mu;
        g_bnMu[c] = mu;
        g_bnInv[c] = rsqrtf(var + 1e-5f);
    }
}

// ---------------- 7: normalize tables ----------------
__global__ void k_bnnorm(const float* __restrict__ gS, const float* __restrict__ beS,
                         const float* __restrict__ gD, const float* __restrict__ beD) {
    int t = blockIdx.x * 256 + threadIdx.x;   // 2048*64
    int a = t >> 6, c = t & 63;
    int cc = c & 31;
    if (c < 32) {
        float x = g_rawS[a * NINP + cc];
        g_hsT[a * NINP + cc] = gS[cc] * (x - g_bnMu[c]) * g_bnInv[c] + beS[cc];
    } else {
        float x = g_rawD[a * NINP + cc];
        g_htT[a * NINP + cc] = gD[cc] * (x - g_bnMu[c]) * g_bnInv[c] + beD[cc];
    }
}

// ---------------- 8: exclusive scan of u-histogram (counting sort) ----------
__global__ void k_scan() {
    __shared__ int sums[256];
    int tid = threadIdx.x;
    int loc[8]; int s = 0;
    #pragma unroll
    for (int i = 0; i < 8; i++) { loc[i] = s; s += g_cntU[tid * 8 + i]; }
    sums[tid] = s;
    __syncthreads();
    if (tid == 0) {
        int run = 0;
        for (int i = 0; i < 256; i++) { int tmp = sums[i]; sums[i] = run; run += tmp; }
    }
    __syncthreads();
    int off = sums[tid];
    #pragma unroll
    for (int i = 0; i < 8; i++) {
        int st = off + loc[i];
        g_start[tid * 8 + i] = st;
        g_cursor[tid * 8 + i] = st;
    }
    if (tid == 255) g_start[NA] = E_;
}

// ---------------- 9: scatter edges into u-buckets ----------------
__global__ void k_scatter(const int* __restrict__ u) {
    int e = blockIdx.x * 256 + threadIdx.x;
    int p = atomicAdd(&g_cursor[u[e]], 1);
    g_perm[p] = e;
}

// ---------------- 10a: C[a,rh] = hs[a,:]·v1[rh,:] + b[rh] -------------------
__global__ void __launch_bounds__(256)
k_cinit(const float* __restrict__ V, const float* __restrict__ Bb) {
    int rh = threadIdx.x;
    int a0 = blockIdx.x * 16;                 // grid 128
    u64 v1r[16];
    const u64* vp = (const u64*)(V + rh * 64);
    #pragma unroll
    for (int q = 0; q < 16; q++) v1r[q] = vp[q];
    float bb = Bb[rh];
    __shared__ float hsm2[16 * 32];           // 16 hs rows
    hsm2[rh]       = g_hsT[a0 * NINP + rh];
    hsm2[rh + 256] = g_hsT[a0 * NINP + rh + 256];
    __syncthreads();
    #pragma unroll
    for (int i = 0; i < 16; i++) {
        const u64* h2 = (const u64*)(hsm2 + i * 32);
        u64 acc0 = 0, acc1 = 0;
        #pragma unroll
        for (int q = 0; q < 16; q += 2) {
            acc0 = ffma2(v1r[q+0], h2[q+0], acc0);
            acc1 = ffma2(v1r[q+1], h2[q+1], acc1);
        }
        g_C[(a0 + i) * NRH + rh] = bb + hsum2(acc0) + hsum2(acc1);
    }
}

// ---------------- 10b: A'[a,rh,j] = hs[a,:]·W[rh,:,j] + v2[rh,j] ------------
__global__ void __launch_bounds__(256)
k_agemm(const float* __restrict__ W, const float* __restrict__ V) {
    int rh = blockIdx.x;                      // 0..255
    int jj = threadIdx.x & 31, ar = threadIdx.x >> 5;   // ar 0..7
    u64 w2[16];
    #pragma unroll
    for (int k = 0; k < 16; k++) {
        float wl = W[rh * 1024 + (2*k)   * 32 + jj];
        float wh = W[rh * 1024 + (2*k+1) * 32 + jj];
        unsigned lo = __float_as_uint(wl), hi = __float_as_uint(wh);
        w2[k] = ((u64)hi << 32) | lo;
    }
    float v2c = V[rh * 64 + 32 + jj];
    __shared__ float4 hsr4[16][8];            // 16 a-rows x 32 floats
    int a0beg = blockIdx.y * (NA / 2);
    for (int a0 = a0beg; a0 < a0beg + NA / 2; a0 += 16) {
        int t = threadIdx.x;
        ((float*)hsr4)[t]       = g_hsT[a0 * NINP + t];
        ((float*)hsr4)[t + 256] = g_hsT[a0 * NINP + t + 256];
        __syncthreads();
        const u64* hA = (const u64*)hsr4[ar];
        const u64* hB = (const u64*)hsr4[ar + 8];
        u64 pa0 = 0, pa1 = 0, pb0 = 0, pb1 = 0;
        #pragma unroll
        for (int k = 0; k < 16; k += 2) {
            pa0 = ffma2(w2[k+0], hA[k+0], pa0);
            pa1 = ffma2(w2[k+1], hA[k+1], pa1);
            pb0 = ffma2(w2[k+0], hB[k+0], pb0);
            pb1 = ffma2(w2[k+1], hB[k+1], pb1);
        }
        g_Ap[(size_t)(a0 + ar)     * 8192 + rh * 32 + jj] = v2c + hsum2(pa0) + hsum2(pa1);
        g_Ap[(size_t)(a0 + ar + 8) * 8192 + rh * 32 + jj] = v2c + hsum2(pb0) + hsum2(pb1);
        __syncthreads();
    }
}

// ---------------- 11: per-edge dot; stats only (no z store) -----------------
__global__ void __launch_bounds__(256)
k_edgestats(const int* __restrict__ v) {
    int a  = blockIdx.x;                      // u-bucket
    int rh = threadIdx.x;
    u64 areg[16];
    const u64* ap = (const u64*)(g_Ap + (size_t)a * 8192 + rh * 32);
    #pragma unroll
    for (int q = 0; q < 16; q++) areg[q] = ap[q];
    float cinit = g_C[a * NRH + rh];
    int s = g_start[a], eend = g_start[a + 1];
    float s1 = 0.f, s2 = 0.f;
    __shared__ float4 hts4[8][8];
    for (int p0 = s; p0 < eend; p0 += 8) {
        int nb = min(8, eend - p0);
        if (rh < nb * 32) {
            int g = rh >> 5, lj = rh & 31;
            int e = g_perm[p0 + g];
            ((float*)hts4[g])[lj] = g_htT[v[e] * NINP + lj];
        }
        __syncthreads();
        for (int q = 0; q < nb; q++) {
            const u64* hp = (const u64*)hts4[q];
            u64 p0a = 0, p1a = 0;
            #pragma unroll
            for (int i = 0; i < 16; i += 2) {
                p0a = ffma2(areg[i+0], hp[i+0], p0a);
                p1a = ffma2(areg[i+1], hp[i+1], p1a);
            }
            float acc = cinit + hsum2(p0a) + hsum2(p1a);
            s1 += acc; s2 += acc * acc;
        }
        __syncthreads();
    }
    if (eend > s) {
        atomicAdd(&g_zsum[rh], s1);
        atomicAdd(&g_zsq[rh],  s2);
    }
}

// ---------------- 12: finalize z layernorm params ----------------
__global__ void k_zstats(const float* __restrict__ gg, const float* __restrict__ be) {
    int rh = threadIdx.x;
    float mu  = g_zsum[rh] * (1.0f / E_);
    float var = g_zsq[rh] * (1.0f / E_) - mu * mu;
    float inv = rsqrtf(var + 1e-5f);
    float sc  = gg[rh] * inv;
    g_zscale[rh] = sc;
    g_zoff[rh]   = be[rh] - sc * mu;
}

// ---------------- 13: fused recompute + tanh + relation reduce -> logits ----
__global__ void __launch_bounds__(256)
k_final(const int* __restrict__ v, const float* __restrict__ uu,
        float* __restrict__ out) {
    int a  = blockIdx.x;                      // u-bucket
    int rh = threadIdx.x;
    u64 areg[16];
    const u64* ap = (const u64*)(g_Ap + (size_t)a * 8192 + rh * 32);
    #pragma unroll
    for (int q = 0; q < 16; q++) areg[q] = ap[q];
    float cinit = g_C[a * NRH + rh];
    float sc = g_zscale[rh], of = g_zoff[rh], ur = uu[rh];
    int s = g_start[a], eend = g_start[a + 1];
    __shared__ float4 hts4[8][8];
    __shared__ int eid[8];
    for (int p0 = s; p0 < eend; p0 += 8) {
        int nb = min(8, eend - p0);
        if (rh < nb * 32) {
            int g = rh >> 5, lj = rh & 31;
            int e = g_perm[p0 + g];
            if (lj == 0) eid[g] = e;
            ((float*)hts4[g])[lj] = g_htT[v[e] * NINP + lj];
        }
        __syncthreads();
        for (int q = 0; q < nb; q++) {
            const u64* hp = (const u64*)hts4[q];
            u64 p0a = 0, p1a = 0;
            #pragma unroll
            for (int i = 0; i < 16; i += 2) {
                p0a = ffma2(areg[i+0], hp[i+0], p0a);
                p1a = ffma2(areg[i+1], hp[i+1], p1a);
            }
            float z = cinit + hsum2(p0a) + hsum2(p1a);
            float val = ur * tanha(fmaf(sc, z, of));
            val += __shfl_xor_sync(0xffffffffu, val, 1);
            val += __shfl_xor_sync(0xffffffffu, val, 2);
            val += __shfl_xor_sync(0xffffffffu, val, 4);
            val += __shfl_xor_sync(0xffffffffu, val, 8);
            if ((rh & 15) == 0) out[(size_t)eid[q] * 16 + (rh >> 4)] = val;
        }
        __syncthreads();
    }
}

// ---------------- launch ----------------
extern "C" void kernel_launch(void* const* d_in, const int* in_sizes, int n_in,
                              void* d_out, int out_size) {
    const int*   seq  = (const int*)d_in[0];
    const int*   p2g  = (const int*)d_in[1];
    const int*   idx  = (const int*)d_in[2];
    const int*   u    = (const int*)d_in[3];
    const int*   v    = (const int*)d_in[4];
    const float* emb  = (const float*)d_in[5];
    const float* wihF = (const float*)d_in[6];
    const float* whhF = (const float*)d_in[7];
    const float* bihF = (const float*)d_in[8];
    const float* bhhF = (const float*)d_in[9];
    const float* wihB = (const float*)d_in[10];
    const float* whhB = (const float*)d_in[11];
    const float* bihB = (const float*)d_in[12];
    const float* bhhB = (const float*)d_in[13];
    const float* wS   = (const float*)d_in[14];
    const float* bS   = (const float*)d_in[15];
    const float* wD   = (const float*)d_in[16];
    const float* bD   = (const float*)d_in[17];
    const float* gS   = (const float*)d_in[18];
    const float* beS  = (const float*)d_in[19];
    const float* gD   = (const float*)d_in[20];
    const float* beD  = (const float*)d_in[21];
    const float* ntlW = (const float*)d_in[22];
    const float* ntlV = (const float*)d_in[23];
    const float* ntlB = (const float*)d_in[24];
    const float* ntlU = (const float*)d_in[25];
    const float* ntlG = (const float*)d_in[26];
    const float* ntlBe= (const float*)d_in[27];
    float* out = (float*)d_out;

    k_init     <<<8, 256>>>();
    k_embed    <<<64, 256>>>(seq, p2g, emb);
    k_histo    <<<256, 256>>>(u, v);
    k_xproj    <<<256, 256>>>(wihF, bihF, bhhF, wihB, bihB, bhhB);
    k_lstm     <<<64, 512>>>(whhF, whhB);
    k_nodeproj <<<2048, 64>>>(p2g, idx, wS, bS, wD, bD);
    k_bnstats  <<<64, 256>>>();
    k_bnnorm   <<<512, 256>>>(gS, beS, gD, beD);
    k_scan     <<<1, 256>>>();
    k_scatter  <<<256, 256>>>(u);
    k_cinit    <<<128, 256>>>(ntlV, ntlB);
    k_agemm    <<<dim3(256, 2), 256>>>(ntlW, ntlV);
    k_edgestats<<<2048, 256>>>(v);
    k_zstats   <<<1, 256>>>(ntlG, ntlBe);
    k_final    <<<2048, 256>>>(v, ntlU, out);
}

// round 7
// speedup vs baseline: 1.2115x; 1.2115x over previous
#include <cuda_runtime.h>
#include <cuda_bf16.h>

// ---------------- problem constants ----------------
#define B_    64
#define L_    512
#define G_    128
#define N_    32
#define K_    8
#define E_    65536
#define DTOK  64
#define H_    64
#define NINP  32
#define NRH   256          // NREL*NHID = 16*16
#define NA    2048         // B*N

typedef unsigned long long u64;

// ---------------- scratch (__device__ globals; no allocation) ----------------
__device__ float g_xgrp[B_*G_*DTOK];        // (B,G,64)
__device__ float g_gx[128*G_*256];          // (bid, t, gate) 16.7MB
__device__ float g_hgrp[B_*G_*2*H_];        // (B,G,128)  fwd[0:64) bwd[64:128)
__device__ float g_rawS[NA*NINP];
__device__ float g_rawD[NA*NINP];
__device__ float g_hsT [NA*NINP];
__device__ float g_htT [NA*NINP];
__device__ int   g_cntU[NA];
__device__ int   g_cntV[NA];
__device__ int   g_start[NA+1];
__device__ int   g_cursor[NA];
__device__ int   g_perm[E_];
__device__ float g_bnMu[64];
__device__ float g_bnInv[64];
__device__ float g_Ap[(size_t)NA*NRH*32];   // 64 MB
__device__ float g_C [NA*NRH];
__device__ float g_zsum[NRH];
__device__ float g_zsq [NRH];
__device__ float g_z[(size_t)E_*NRH];       // 64 MB, layout (E, 256)

// ---------------- math helpers ----------------
__device__ __forceinline__ float tanha(float x) {           // MUFU.TANH
    float y; asm("tanh.approx.f32 %0, %1;" : "=f"(y) : "f"(x)); return y;
}
__device__ __forceinline__ float siga(float x) {            // exact identity
    return fmaf(0.5f, tanha(0.5f * x), 0.5f);
}
__device__ __forceinline__ u64 ffma2(u64 a, u64 b, u64 c) { // packed f32x2 FMA
    u64 d; asm("fma.rn.f32x2 %0, %1, %2, %3;" : "=l"(d) : "l"(a), "l"(b), "l"(c));
    return d;
}
__device__ __forceinline__ float hsum2(u64 x) {
    return __uint_as_float((unsigned)(x & 0xffffffffull)) +
           __uint_as_float((unsigned)(x >> 32));
}

// ---------------- 1: zero counters ----------------
__global__ void k_init() {
    int t = blockIdx.x * 256 + threadIdx.x;
    if (t < NA)  { g_cntU[t] = 0; g_cntV[t] = 0; }
    if (t < NRH) { g_zsum[t] = 0.f; g_zsq[t] = 0.f; }
}

// ---------------- 2: token embed + scatter-sum + edge histograms ------------
__global__ void k_embed(const int* __restrict__ seq, const int* __restrict__ p2g,
                        const float* __restrict__ emb,
                        const int* __restrict__ u, const int* __restrict__ v) {
    __shared__ float acc[G_ * DTOK];          // 32 KB
    int b = blockIdx.x;
    int tid = threadIdx.x;                    // 256
    for (int i = tid; i < G_ * DTOK; i += 256) acc[i] = 0.f;
    __syncthreads();
    int sub  = tid & 15;                      // 16 threads per token (float4 each)
    int tok0 = tid >> 4;
    for (int l = tok0; l < L_; l += 16) {
        int s = seq[b * L_ + l];
        int g = p2g[b * L_ + l];
        float4 x4 = ((const float4*)(emb + (size_t)s * DTOK))[sub];
        float* dst = acc + g * DTOK + sub * 4;
        atomicAdd(dst + 0, x4.x); atomicAdd(dst + 1, x4.y);
        atomicAdd(dst + 2, x4.z); atomicAdd(dst + 3, x4.w);
    }
    __syncthreads();
    for (int i = tid; i < G_ * DTOK; i += 256) g_xgrp[b * G_ * DTOK + i] = acc[i];
    // fused edge-endpoint histograms (counters zeroed by k_init, prior launch)
    int base = (b * 256 + tid) * 4;
    #pragma unroll
    for (int k = 0; k < 4; k++) {
        atomicAdd(&g_cntU[u[base + k]], 1);
        atomicAdd(&g_cntV[v[base + k]], 1);
    }
}

// ---------------- 3: input projection gx[bid][t][gate], 128 CTAs, 2-t ILP ---
__global__ void __launch_bounds__(256)
k_xproj(const float* __restrict__ wihF, const float* __restrict__ bihF,
        const float* __restrict__ bhhF,
        const float* __restrict__ wihB, const float* __restrict__ bihB,
        const float* __restrict__ bhhB) {
    int bid = blockIdx.x;                     // 0..127
    int b   = bid & 63;
    int dir = bid >> 6;
    const float* wih = dir ? wihB : wihF;
    const float* bih = dir ? bihB : bihF;
    const float* bhh = dir ? bhhB : bhhF;
    int j = threadIdx.x;                      // gate row

    __shared__ u64 xsm[G_ * DTOK / 2];        // 32 KB: all 128 timesteps
    const u64* src = (const u64*)(g_xgrp + b * G_ * DTOK);
    #pragma unroll
    for (int i = 0; i < 16; i++) xsm[j + i * 256] = src[j + i * 256];

    u64 wi2[32];
    const u64* wip = (const u64*)(wih + j * DTOK);
    #pragma unroll
    for (int k = 0; k < 32; k++) wi2[k] = wip[k];
    float bias = bih[j] + bhh[j];
    __syncthreads();

    float* dst = g_gx + (size_t)bid * G_ * 256 + j;
    for (int t = 0; t < G_; t += 2) {
        int tgA = dir ? (G_ - 1 - t) : t;
        int tgB = dir ? (G_ - 2 - t) : (t + 1);
        const u64* xa = xsm + tgA * 32;
        const u64* xb = xsm + tgB * 32;
        u64 a0 = 0, a1 = 0, a2 = 0, a3 = 0;
        u64 c0 = 0, c1 = 0, c2 = 0, c3 = 0;
        #pragma unroll
        for (int k = 0; k < 32; k += 4) {
            a0 = ffma2(wi2[k+0], xa[k+0], a0);
            a1 = ffma2(wi2[k+1], xa[k+1], a1);
            a2 = ffma2(wi2[k+2], xa[k+2], a2);
            a3 = ffma2(wi2[k+3], xa[k+3], a3);
            c0 = ffma2(wi2[k+0], xb[k+0], c0);
            c1 = ffma2(wi2[k+1], xb[k+1], c1);
            c2 = ffma2(wi2[k+2], xb[k+2], c2);
            c3 = ffma2(wi2[k+3], xb[k+3], c3);
        }
        dst[t * 256]       = bias + (hsum2(a0) + hsum2(a1)) + (hsum2(a2) + hsum2(a3));
        dst[(t + 1) * 256] = bias + (hsum2(c0) + hsum2(c1)) + (hsum2(c2) + hsum2(c3));
    }
}

// ---------------- 4: recurrence, MUFU activations pre-barrier ---------------
__global__ void __launch_bounds__(256, 1)
k_lstm(const float* __restrict__ whhF, const float* __restrict__ whhB) {
    int bid = blockIdx.x;                      // 0..127
    int b   = bid & 63;
    int dir = bid >> 6;
    const float* whh = dir ? whhB : whhF;
    int j = threadIdx.x;                       // gate row 0..255 (i,f,g,o x 64)
    int gate = j >> 6;

    u64 wh2[32];
    const u64* whp = (const u64*)(whh + j * H_);
    #pragma unroll
    for (int k = 0; k < 32; k++) wh2[k] = whp[k];

    __shared__ u64 hsm[32];                    // current h (64 f)
    __shared__ float gsm[256];                 // ACTIVATED gates
    float c = 0.f;
    if (j < 32) hsm[j] = 0ull;

    const float* gx = g_gx + (size_t)bid * G_ * 256 + j;
    float gxr = gx[0];
    __syncthreads();

    for (int t = 0; t < G_; t++) {
        float gxn = gx[(t + 1 < G_ ? t + 1 : t) * 256];   // prefetch
        u64 a0 = 0, a1 = 0, a2 = 0, a3 = 0;
        #pragma unroll
        for (int k = 0; k < 32; k += 4) {
            a0 = ffma2(wh2[k+0], hsm[k+0], a0);
            a1 = ffma2(wh2[k+1], hsm[k+1], a1);
            a2 = ffma2(wh2[k+2], hsm[k+2], a2);
            a3 = ffma2(wh2[k+3], hsm[k+3], a3);
        }
        float pre = gxr + (hsum2(a0) + hsum2(a1)) + (hsum2(a2) + hsum2(a3));
        gsm[j] = (gate == 2) ? tanha(pre) : siga(pre);   // off serial path
        gxr = gxn;
        __syncthreads();
        if (j < 64) {
            float ai = gsm[j],       af = gsm[64 + j];
            float ag = gsm[128 + j], ao = gsm[192 + j];
            c = fmaf(af, c, ai * ag);
            float h = ao * tanha(c);
            ((float*)hsm)[j] = h;
            int tg = dir ? (G_ - 1 - t) : t;
            g_hgrp[(b * G_ + tg) * (2 * H_) + dir * H_ + j] = h;
        }
        __syncthreads();
    }
}

// ---------------- 5: node gather (sum K groups) + endpoint projections -------
__global__ void k_nodeproj(const int* __restrict__ p2g, const int* __restrict__ idx,
                           const float* __restrict__ wS, const float* __restrict__ bS,
                           const float* __restrict__ wD, const float* __restrict__ bD) {
    int a = blockIdx.x;                       // node 0..2047
    int b = a >> 5, n = a & 31;
    int tid = threadIdx.x;                    // 64
    __shared__ float4 hrow4[32];              // 128 floats
    float* hrow = (float*)hrow4;
    float s0 = 0.f, s1 = 0.f;
    #pragma unroll
    for (int k = 0; k < K_; k++) {
        int pos = idx[(b * N_ + n) * K_ + k];
        int g   = p2g[b * L_ + pos];
        const float* hp = g_hgrp + (b * G_ + g) * (2 * H_);
        s0 += hp[tid]; s1 += hp[tid + 64];
    }
    hrow[tid] = s0; hrow[tid + 64] = s1;
    __syncthreads();
    const float* w = (tid < 32) ? (wS + tid * 128) : (wD + (tid - 32) * 128);
    float bb = (tid < 32) ? bS[tid] : bD[tid - 32];
    const u64* h2 = (const u64*)hrow;
    const u64* w2 = (const u64*)w;
    u64 a0 = 0, a1 = 0, a2 = 0, a3 = 0;
    #pragma unroll
    for (int q = 0; q < 64; q += 4) {
        a0 = ffma2(w2[q+0], h2[q+0], a0);
        a1 = ffma2(w2[q+1], h2[q+1], a1);
        a2 = ffma2(w2[q+2], h2[q+2], a2);
        a3 = ffma2(w2[q+3], h2[q+3], a3);
    }
    float acc = bb + (hsum2(a0) + hsum2(a1)) + (hsum2(a2) + hsum2(a3));
    if (tid < 32) g_rawS[a * NINP + tid] = acc;
    else          g_rawD[a * NINP + tid - 32] = acc;
}

// ---------------- 6: BN stats as count-weighted moments (exact) --------------
__global__ void k_bnstats() {
    int c = blockIdx.x;                       // 0..63 (src 0-31, dst 32-63)
    int tid = threadIdx.x;
    const float* raw = (c < 32) ? g_rawS : g_rawD;
    const int*   cnt = (c < 32) ? g_cntU : g_cntV;
    int cc = c & 31;
    float s = 0.f, s2 = 0.f;
    for (int a = tid; a < NA; a += 256) {
        float w = (float)cnt[a];
        float x = raw[a * NINP + cc];
        s += w * x; s2 += w * x * x;
    }
    __shared__ float r1[256], r2[256];
    r1[tid] = s; r2[tid] = s2; __syncthreads();
    for (int o = 128; o > 0; o >>= 1) {
        if (tid < o) { r1[tid] += r1[tid + o]; r2[tid] += r2[tid + o]; }
        __syncthreads();
    }
    if (tid == 0) {
        float mu  = r1[0] * (1.0f / E_);
        float var = r2[0] * (1.0f / E_) - mu * mu;
        g_bnMu[c] = mu;
        g_bnInv[c] = rsqrtf(var + 1e-5f);
    }
}

// ---------------- 7: normalize tables ----------------
__global__ void k_bnnorm(const float* __restrict__ gS, const float* __restrict__ beS,
                         const float* __restrict__ gD, const float* __restrict__ beD) {
    int t = blockIdx.x * 256 + threadIdx.x;   // 2048*64
    int a = t >> 6, c = t & 63;
    int cc = c & 31;
    if (c < 32) {
        float x = g_rawS[a * NINP + cc];
        g_hsT[a * NINP + cc] = gS[cc] * (x - g_bnMu[c]) * g_bnInv[c] + beS[cc];
    } else {
        float x = g_rawD[a * NINP + cc];
        g_htT[a * NINP + cc] = gD[cc] * (x - g_bnMu[c]) * g_bnInv[c] + beD[cc];
    }
}

// ---------------- 8: parallel exclusive scan of u-histogram ----------------
__global__ void k_scan() {
    int tid = threadIdx.x;
    int lane = tid & 31, w = tid >> 5;
    int loc[8]; int s = 0;
    #pragma unroll
    for (int i = 0; i < 8; i++) { loc[i] = s; s += g_cntU[tid * 8 + i]; }
    // inclusive warp scan of per-thread totals
    int vinc = s;
    #pragma unroll
    for (int o = 1; o < 32; o <<= 1) {
        int t2 = __shfl_up_sync(0xffffffffu, vinc, o);
        if (lane >= o) vinc += t2;
    }
    __shared__ int wsum[8];
    if (lane == 31) wsum[w] = vinc;
    __syncthreads();
    if (w == 0 && lane < 8) {
        int x = wsum[lane];
        #pragma unroll
        for (int o = 1; o < 8; o <<= 1) {
            int t2 = __shfl_up_sync(0xffu, x, o);
            if (lane >= o) x += t2;
        }
        wsum[lane] = x;
    }
    __syncthreads();
    int base = (vinc - s) + (w > 0 ? wsum[w - 1] : 0);
    #pragma unroll
    for (int i = 0; i < 8; i++) {
        int st = base + loc[i];
        g_start[tid * 8 + i] = st;
        g_cursor[tid * 8 + i] = st;
    }
    if (tid == 255) g_start[NA] = E_;
}

// ---------------- 9: scatter edges into u-buckets ----------------
__global__ void k_scatter(const int* __restrict__ u) {
    int e = blockIdx.x * 256 + threadIdx.x;
    int p = atomicAdd(&g_cursor[u[e]], 1);
    g_perm[p] = e;
}

// ---------------- 10: A' GEMM (x<256) + C init (x>=256) ----------------
__global__ void __launch_bounds__(256)
k_agemm(const float* __restrict__ W, const float* __restrict__ V,
        const float* __restrict__ Bb) {
    __shared__ float4 hsr4[16][8];            // 2 KB, used by both branches
    if (blockIdx.x < 256) {
        int rh = blockIdx.x;
        int jj = threadIdx.x & 31, ar = threadIdx.x >> 5;   // ar 0..7
        u64 w2[16];
        #pragma unroll
        for (int k = 0; k < 16; k++) {
            float wl = W[rh * 1024 + (2*k)   * 32 + jj];
            float wh = W[rh * 1024 + (2*k+1) * 32 + jj];
            unsigned lo = __float_as_uint(wl), hi = __float_as_uint(wh);
            w2[k] = ((u64)hi << 32) | lo;
        }
        float v2c = V[rh * 64 + 32 + jj];
        int a0beg = blockIdx.y * (NA / 2);
        for (int a0 = a0beg; a0 < a0beg + NA / 2; a0 += 16) {
            int t = threadIdx.x;
            ((float*)hsr4)[t]       = g_hsT[a0 * NINP + t];
            ((float*)hsr4)[t + 256] = g_hsT[a0 * NINP + t + 256];
            __syncthreads();
            const u64* hA = (const u64*)hsr4[ar];
            const u64* hB = (const u64*)hsr4[ar + 8];
            u64 pa0 = 0, pa1 = 0, pb0 = 0, pb1 = 0;
            #pragma unroll
            for (int k = 0; k < 16; k += 2) {
                pa0 = ffma2(w2[k+0], hA[k+0], pa0);
                pa1 = ffma2(w2[k+1], hA[k+1], pa1);
                pb0 = ffma2(w2[k+0], hB[k+0], pb0);
                pb1 = ffma2(w2[k+1], hB[k+1], pb1);
            }
            g_Ap[(size_t)(a0 + ar)     * 8192 + rh * 32 + jj] = v2c + hsum2(pa0) + hsum2(pa1);
            g_Ap[(size_t)(a0 + ar + 8) * 8192 + rh * 32 + jj] = v2c + hsum2(pb0) + hsum2(pb1);
            __syncthreads();
        }
    } else {
        // C init: unit covers 16 a-rows
        int unit = (blockIdx.x - 256) + blockIdx.y * 64;    // 0..127
        int a0 = unit * 16;
        int rh = threadIdx.x;
        u64 v1r[16];
        const u64* vp = (const u64*)(V + rh * 64);
        #pragma unroll
        for (int q = 0; q < 16; q++) v1r[q] = vp[q];
        float bb = Bb[rh];
        float* hsm2 = (float*)hsr4;
        hsm2[rh]       = g_hsT[a0 * NINP + rh];
        hsm2[rh + 256] = g_hsT[a0 * NINP + rh + 256];
        __syncthreads();
        #pragma unroll
        for (int i = 0; i < 16; i++) {
            const u64* h2 = (const u64*)(hsm2 + i * 32);
            u64 acc0 = 0, acc1 = 0;
            #pragma unroll
            for (int q = 0; q < 16; q += 2) {
                acc0 = ffma2(v1r[q+0], h2[q+0], acc0);
                acc1 = ffma2(v1r[q+1], h2[q+1], acc1);
            }
            g_C[(a0 + i) * NRH + rh] = bb + hsum2(acc0) + hsum2(acc1);
        }
    }
}

// ---------------- 11: per-edge dot; z[e,rh]; running z-stats ----------------
__global__ void __launch_bounds__(256)
k_edge(const int* __restrict__ v) {
    int a  = blockIdx.x;                      // u-bucket
    int rh = threadIdx.x;
    u64 areg[16];
    const u64* ap = (const u64*)(g_Ap + (size_t)a * 8192 + rh * 32);
    #pragma unroll
    for (int q = 0; q < 16; q++) areg[q] = ap[q];
    float cinit = g_C[a * NRH + rh];
    int s = g_start[a], eend = g_start[a + 1];
    float s1 = 0.f, s2 = 0.f;
    __shared__ float4 hts4[8][8];
    __shared__ int eid[8];
    for (int p0 = s; p0 < eend; p0 += 8) {
        int nb = min(8, eend - p0);
        if (rh < nb * 32) {
            int g = rh >> 5, lj = rh & 31;
            int e = g_perm[p0 + g];
            if (lj == 0) eid[g] = e;
            ((float*)hts4[g])[lj] = g_htT[v[e] * NINP + lj];
        }
        __syncthreads();
        for (int q = 0; q < nb; q++) {
            const u64* hp = (const u64*)hts4[q];
            u64 p0a = 0, p1a = 0;
            #pragma unroll
            for (int i = 0; i < 16; i += 2) {
                p0a = ffma2(areg[i+0], hp[i+0], p0a);
                p1a = ffma2(areg[i+1], hp[i+1], p1a);
            }
            float acc = cinit + hsum2(p0a) + hsum2(p1a);
            g_z[(size_t)eid[q] * NRH + rh] = acc;
            s1 += acc; s2 += acc * acc;
        }
        __syncthreads();
    }
    if (eend > s) {
        atomicAdd(&g_zsum[rh], s1);
        atomicAdd(&g_zsq[rh],  s2);
    }
}

// ---------------- 12: warp-per-edge tanh + reduce (zstats fused) ------------
__global__ void __launch_bounds__(256)
k_final(const float* __restrict__ gg, const float* __restrict__ be,
        const float* __restrict__ uu, float* __restrict__ out) {
    __shared__ float ssc[256], sof[256], su[256];
    int tid = threadIdx.x;
    {   // fused z layernorm params (deterministic, recomputed per CTA)
        float mu  = g_zsum[tid] * (1.0f / E_);
        float var = g_zsq[tid] * (1.0f / E_) - mu * mu;
        float sc  = gg[tid] * rsqrtf(var + 1e-5f);
        ssc[tid] = sc;
        sof[tid] = be[tid] - sc * mu;
        su[tid]  = uu[tid];
    }
    __syncthreads();
    int w = tid >> 5, l = tid & 31;
    int rh0 = l * 8;
    float sc0 = ssc[rh0+0], sc1 = ssc[rh0+1], sc2 = ssc[rh0+2], sc3 = ssc[rh0+3];
    float sc4 = ssc[rh0+4], sc5 = ssc[rh0+5], sc6 = ssc[rh0+6], sc7 = ssc[rh0+7];
    float of0 = sof[rh0+0], of1 = sof[rh0+1], of2 = sof[rh0+2], of3 = sof[rh0+3];
    float of4 = sof[rh0+4], of5 = sof[rh0+5], of6 = sof[rh0+6], of7 = sof[rh0+7];
    float u0 = su[rh0+0], u1 = su[rh0+1], u2 = su[rh0+2], u3 = su[rh0+3];
    float u4 = su[rh0+4], u5 = su[rh0+5], u6 = su[rh0+6], u7 = su[rh0+7];
    int e0 = blockIdx.x * 64 + w * 8;
    #pragma unroll
    for (int i = 0; i < 8; i++) {
        int e = e0 + i;
        const float4* zp = (const float4*)(g_z + (size_t)e * NRH) + l * 2;
        float4 za = zp[0], zb = zp[1];
        float s =  u0 * tanha(fmaf(sc0, za.x, of0));
        s += u1 * tanha(fmaf(sc1, za.y, of1));
        s += u2 * tanha(fmaf(sc2, za.z, of2));
        s += u3 * tanha(fmaf(sc3, za.w, of3));
        s += u4 * tanha(fmaf(sc4, zb.x, of4));
        s += u5 * tanha(fmaf(sc5, zb.y, of5));
        s += u6 * tanha(fmaf(sc6, zb.z, of6));
        s += u7 * tanha(fmaf(sc7, zb.w, of7));
        s += __shfl_xor_sync(0xffffffffu, s, 1);
        if ((l & 1) == 0) out[(size_t)e * 16 + (l >> 1)] = s;
    }
}

// ---------------- launch ----------------
extern "C" void kernel_launch(void* const* d_in, const int* in_sizes, int n_in,
                              void* d_out, int out_size) {
    const int*   seq  = (const int*)d_in[0];
    const int*   p2g  = (const int*)d_in[1];
    const int*   idx  = (const int*)d_in[2];
    const int*   u    = (const int*)d_in[3];
    const int*   v    = (const int*)d_in[4];
    const float* emb  = (const float*)d_in[5];
    const float* wihF = (const float*)d_in[6];
    const float* whhF = (const float*)d_in[7];
    const float* bihF = (const float*)d_in[8];
    const float* bhhF = (const float*)d_in[9];
    const float* wihB = (const float*)d_in[10];
    const float* whhB = (const float*)d_in[11];
    const float* bihB = (const float*)d_in[12];
    const float* bhhB = (const float*)d_in[13];
    const float* wS   = (const float*)d_in[14];
    const float* bS   = (const float*)d_in[15];
    const float* wD   = (const float*)d_in[16];
    const float* bD   = (const float*)d_in[17];
    const float* gS   = (const float*)d_in[18];
    const float* beS  = (const float*)d_in[19];
    const float* gD   = (const float*)d_in[20];
    const float* beD  = (const float*)d_in[21];
    const float* ntlW = (const float*)d_in[22];
    const float* ntlV = (const float*)d_in[23];
    const float* ntlB = (const float*)d_in[24];
    const float* ntlU = (const float*)d_in[25];
    const float* ntlG = (const float*)d_in[26];
    const float* ntlBe= (const float*)d_in[27];
    float* out = (float*)d_out;

    k_init     <<<8, 256>>>();
    k_embed    <<<64, 256>>>(seq, p2g, emb, u, v);
    k_xproj    <<<128, 256>>>(wihF, bihF, bhhF, wihB, bihB, bhhB);
    k_lstm     <<<128, 256>>>(whhF, whhB);
    k_nodeproj <<<2048, 64>>>(p2g, idx, wS, bS, wD, bD);
    k_bnstats  <<<64, 256>>>();
    k_bnnorm   <<<512, 256>>>(gS, beS, gD, beD);
    k_scan     <<<1, 256>>>();
    k_scatter  <<<256, 256>>>(u);
    k_agemm    <<<dim3(320, 2), 256>>>(ntlW, ntlV, ntlB);
    k_edge     <<<2048, 256>>>(v);
    k_final    <<<1024, 256>>>(ntlG, ntlBe, ntlU, out);
}

// round 8
// speedup vs baseline: 1.2180x; 1.0054x over previous
#include <cuda_runtime.h>
#include <cuda_bf16.h>

// ---------------- problem constants ----------------
#define B_    64
#define L_    512
#define G_    128
#define N_    32
#define K_    8
#define E_    65536
#define DTOK  64
#define H_    64
#define NINP  32
#define NRH   256          // NREL*NHID = 16*16
#define NA    2048         // B*N

typedef unsigned long long u64;

// ---------------- scratch (__device__ globals; no allocation) ----------------
__device__ float g_xgrp[B_*G_*DTOK];        // (B,G,64)
__device__ float g_gx[128*G_*256];          // (bid, t, gate) 16.7MB
__device__ float g_hgrp[B_*G_*2*H_];        // (B,G,128)  fwd[0:64) bwd[64:128)
__device__ float g_rawS[NA*NINP];
__device__ float g_rawD[NA*NINP];
__device__ float g_hsT [NA*NINP];
__device__ float g_htT [NA*NINP];
__device__ int   g_cntU[NA];
__device__ int   g_cntV[NA];
__device__ int   g_start[NA+1];
__device__ int   g_cursor[NA];
__device__ int   g_perm[E_];
__device__ float g_bnMu[64];
__device__ float g_bnInv[64];
__device__ float g_Ap[(size_t)NA*NRH*32];   // 64 MB
__device__ float g_C [NA*NRH];
__device__ float g_zsum[NRH];
__device__ float g_zsq [NRH];
__device__ float g_z[(size_t)E_*NRH];       // 64 MB, layout (E, 256)

// ---------------- math helpers ----------------
__device__ __forceinline__ float tanha(float x) {           // MUFU.TANH
    float y; asm("tanh.approx.f32 %0, %1;" : "=f"(y) : "f"(x)); return y;
}
__device__ __forceinline__ float siga(float x) {            // exact identity
    return fmaf(0.5f, tanha(0.5f * x), 0.5f);
}
__device__ __forceinline__ u64 ffma2(u64 a, u64 b, u64 c) { // packed f32x2 FMA
    u64 d; asm("fma.rn.f32x2 %0, %1, %2, %3;" : "=l"(d) : "l"(a), "l"(b), "l"(c));
    return d;
}
__device__ __forceinline__ float hsum2(u64 x) {
    return __uint_as_float((unsigned)(x & 0xffffffffull)) +
           __uint_as_float((unsigned)(x >> 32));
}

// ---------------- 1: zero counters ----------------
__global__ void k_init() {
    int t = blockIdx.x * 256 + threadIdx.x;
    if (t < NA)  { g_cntU[t] = 0; g_cntV[t] = 0; }
    if (t < NRH) { g_zsum[t] = 0.f; g_zsq[t] = 0.f; }
}

// ---------------- 2: token embed + scatter-sum + edge histograms ------------
__global__ void k_embed(const int* __restrict__ seq, const int* __restrict__ p2g,
                        const float* __restrict__ emb,
                        const int* __restrict__ u, const int* __restrict__ v) {
    __shared__ float acc[G_ * DTOK];          // 32 KB
    int b = blockIdx.x;
    int tid = threadIdx.x;                    // 256
    for (int i = tid; i < G_ * DTOK; i += 256) acc[i] = 0.f;
    __syncthreads();
    int sub  = tid & 15;                      // 16 threads per token (float4 each)
    int tok0 = tid >> 4;
    for (int l = tok0; l < L_; l += 16) {
        int s = seq[b * L_ + l];
        int g = p2g[b * L_ + l];
        float4 x4 = ((const float4*)(emb + (size_t)s * DTOK))[sub];
        float* dst = acc + g * DTOK + sub * 4;
        atomicAdd(dst + 0, x4.x); atomicAdd(dst + 1, x4.y);
        atomicAdd(dst + 2, x4.z); atomicAdd(dst + 3, x4.w);
    }
    __syncthreads();
    for (int i = tid; i < G_ * DTOK; i += 256) g_xgrp[b * G_ * DTOK + i] = acc[i];
    // fused edge-endpoint histograms (counters zeroed by k_init, prior launch)
    int base = (b * 256 + tid) * 4;
    #pragma unroll
    for (int k = 0; k < 4; k++) {
        atomicAdd(&g_cntU[u[base + k]], 1);
        atomicAdd(&g_cntV[v[base + k]], 1);
    }
}

// ---------------- 3: input projection gx[bid][t][gate], 128 CTAs, 2-t ILP ---
__global__ void __launch_bounds__(256)
k_xproj(const float* __restrict__ wihF, const float* __restrict__ bihF,
        const float* __restrict__ bhhF,
        const float* __restrict__ wihB, const float* __restrict__ bihB,
        const float* __restrict__ bhhB) {
    int bid = blockIdx.x;                     // 0..127
    int b   = bid & 63;
    int dir = bid >> 6;
    const float* wih = dir ? wihB : wihF;
    const float* bih = dir ? bihB : bihF;
    const float* bhh = dir ? bhhB : bhhF;
    int j = threadIdx.x;                      // gate row

    __shared__ u64 xsm[G_ * DTOK / 2];        // 32 KB: all 128 timesteps
    const u64* src = (const u64*)(g_xgrp + b * G_ * DTOK);
    #pragma unroll
    for (int i = 0; i < 16; i++) xsm[j + i * 256] = src[j + i * 256];

    u64 wi2[32];
    const u64* wip = (const u64*)(wih + j * DTOK);
    #pragma unroll
    for (int k = 0; k < 32; k++) wi2[k] = wip[k];
    float bias = bih[j] + bhh[j];
    __syncthreads();

    float* dst = g_gx + (size_t)bid * G_ * 256 + j;
    for (int t = 0; t < G_; t += 2) {
        int tgA = dir ? (G_ - 1 - t) : t;
        int tgB = dir ? (G_ - 2 - t) : (t + 1);
        const u64* xa = xsm + tgA * 32;
        const u64* xb = xsm + tgB * 32;
        u64 a0 = 0, a1 = 0, a2 = 0, a3 = 0;
        u64 c0 = 0, c1 = 0, c2 = 0, c3 = 0;
        #pragma unroll
        for (int k = 0; k < 32; k += 4) {
            a0 = ffma2(wi2[k+0], xa[k+0], a0);
            a1 = ffma2(wi2[k+1], xa[k+1], a1);
            a2 = ffma2(wi2[k+2], xa[k+2], a2);
            a3 = ffma2(wi2[k+3], xa[k+3], a3);
            c0 = ffma2(wi2[k+0], xb[k+0], c0);
            c1 = ffma2(wi2[k+1], xb[k+1], c1);
            c2 = ffma2(wi2[k+2], xb[k+2], c2);
            c3 = ffma2(wi2[k+3], xb[k+3], c3);
        }
        dst[t * 256]       = bias + (hsum2(a0) + hsum2(a1)) + (hsum2(a2) + hsum2(a3));
        dst[(t + 1) * 256] = bias + (hsum2(c0) + hsum2(c1)) + (hsum2(c2) + hsum2(c3));
    }
}

// ---------------- 4: recurrence, MUFU activations pre-barrier ---------------
__global__ void __launch_bounds__(256, 1)
k_lstm(const float* __restrict__ whhF, const float* __restrict__ whhB) {
    int bid = blockIdx.x;                      // 0..127
    int b   = bid & 63;
    int dir = bid >> 6;
    const float* whh = dir ? whhB : whhF;
    int j = threadIdx.x;                       // gate row 0..255 (i,f,g,o x 64)
    int gate = j >> 6;

    u64 wh2[32];
    const u64* whp = (const u64*)(whh + j * H_);
    #pragma unroll
    for (int k = 0; k < 32; k++) wh2[k] = whp[k];

    __shared__ u64 hsm[32];                    // current h (64 f)
    __shared__ float gsm[256];                 // ACTIVATED gates
    float c = 0.f;
    if (j < 32) hsm[j] = 0ull;

    const float* gx = g_gx + (size_t)bid * G_ * 256 + j;
    float gxr = gx[0];
    __syncthreads();

    for (int t = 0; t < G_; t++) {
        float gxn = gx[(t + 1 < G_ ? t + 1 : t) * 256];   // prefetch
        u64 a0 = 0, a1 = 0, a2 = 0, a3 = 0;
        #pragma unroll
        for (int k = 0; k < 32; k += 4) {
            a0 = ffma2(wh2[k+0], hsm[k+0], a0);
            a1 = ffma2(wh2[k+1], hsm[k+1], a1);
            a2 = ffma2(wh2[k+2], hsm[k+2], a2);
            a3 = ffma2(wh2[k+3], hsm[k+3], a3);
        }
        float pre = gxr + (hsum2(a0) + hsum2(a1)) + (hsum2(a2) + hsum2(a3));
        gsm[j] = (gate == 2) ? tanha(pre) : siga(pre);   // off serial path
        gxr = gxn;
        __syncthreads();
        if (j < 64) {
            float ai = gsm[j],       af = gsm[64 + j];
            float ag = gsm[128 + j], ao = gsm[192 + j];
            c = fmaf(af, c, ai * ag);
            float h = ao * tanha(c);
            ((float*)hsm)[j] = h;
            int tg = dir ? (G_ - 1 - t) : t;
            g_hgrp[(b * G_ + tg) * (2 * H_) + dir * H_ + j] = h;
        }
        __syncthreads();
    }
}

// ---------------- 5: node gather (sum K groups) + endpoint projections -------
__global__ void k_nodeproj(const int* __restrict__ p2g, const int* __restrict__ idx,
                           const float* __restrict__ wS, const float* __restrict__ bS,
                           const float* __restrict__ wD, const float* __restrict__ bD) {
    int a = blockIdx.x;                       // node 0..2047
    int b = a >> 5, n = a & 31;
    int tid = threadIdx.x;                    // 64
    __shared__ float4 hrow4[32];              // 128 floats
    float* hrow = (float*)hrow4;
    float s0 = 0.f, s1 = 0.f;
    #pragma unroll
    for (int k = 0; k < K_; k++) {
        int pos = idx[(b * N_ + n) * K_ + k];
        int g   = p2g[b * L_ + pos];
        const float* hp = g_hgrp + (b * G_ + g) * (2 * H_);
        s0 += hp[tid]; s1 += hp[tid + 64];
    }
    hrow[tid] = s0; hrow[tid + 64] = s1;
    __syncthreads();
    const float* w = (tid < 32) ? (wS + tid * 128) : (wD + (tid - 32) * 128);
    float bb = (tid < 32) ? bS[tid] : bD[tid - 32];
    const u64* h2 = (const u64*)hrow;
    const u64* w2 = (const u64*)w;
    u64 a0 = 0, a1 = 0, a2 = 0, a3 = 0;
    #pragma unroll
    for (int q = 0; q < 64; q += 4) {
        a0 = ffma2(w2[q+0], h2[q+0], a0);
        a1 = ffma2(w2[q+1], h2[q+1], a1);
        a2 = ffma2(w2[q+2], h2[q+2], a2);
        a3 = ffma2(w2[q+3], h2[q+3], a3);
    }
    float acc = bb + (hsum2(a0) + hsum2(a1)) + (hsum2(a2) + hsum2(a3));
    if (tid < 32) g_rawS[a * NINP + tid] = acc;
    else          g_rawD[a * NINP + tid - 32] = acc;
}

// ---------------- 6: BN stats as count-weighted moments (exact) --------------
__global__ void k_bnstats() {
    int c = blockIdx.x;                       // 0..63 (src 0-31, dst 32-63)
    int tid = threadIdx.x;
    const float* raw = (c < 32) ? g_rawS : g_rawD;
    const int*   cnt = (c < 32) ? g_cntU : g_cntV;
    int cc = c & 31;
    float s = 0.f, s2 = 0.f;
    for (int a = tid; a < NA; a += 256) {
        float w = (float)cnt[a];
        float x = raw[a * NINP + cc];
        s += w * x; s2 += w * x * x;
    }
    __shared__ float r1[256], r2[256];
    r1[tid] = s; r2[tid] = s2; __syncthreads();
    for (int o = 128; o > 0; o >>= 1) {
        if (tid < o) { r1[tid] += r1[tid + o]; r2[tid] += r2[tid + o]; }
        __syncthreads();
    }
    if (tid == 0) {
        float mu  = r1[0] * (1.0f / E_);
        float var = r2[0] * (1.0f / E_) - mu * mu;
        g_bnMu[c] = mu;
        g_bnInv[c] = rsqrtf(var + 1e-5f);
    }
}

// ---------------- 7: normalize tables ----------------
__global__ void k_bnnorm(const float* __restrict__ gS, const float* __restrict__ beS,
                         const float* __restrict__ gD, const float* __restrict__ beD) {
    int t = blockIdx.x * 256 + threadIdx.x;   // 2048*64
    int a = t >> 6, c = t & 63;
    int cc = c & 31;
    if (c < 32) {
        float x = g_rawS[a * NINP + cc];
        g_hsT[a * NINP + cc] = gS[cc] * (x - g_bnMu[c]) * g_bnInv[c] + beS[cc];
    } else {
        float x = g_rawD[a * NINP + cc];
        g_htT[a * NINP + cc] = gD[cc] * (x - g_bnMu[c]) * g_bnInv[c] + beD[cc];
    }
}

// ---------------- 8: parallel exclusive scan of u-histogram ----------------
__global__ void k_scan() {
    int tid = threadIdx.x;
    int lane = tid & 31, w = tid >> 5;
    int loc[8]; int s = 0;
    #pragma unroll
    for (int i = 0; i < 8; i++) { loc[i] = s; s += g_cntU[tid * 8 + i]; }
    // inclusive warp scan of per-thread totals
    int vinc = s;
    #pragma unroll
    for (int o = 1; o < 32; o <<= 1) {
        int t2 = __shfl_up_sync(0xffffffffu, vinc, o);
        if (lane >= o) vinc += t2;
    }
    __shared__ int wsum[8];
    if (lane == 31) wsum[w] = vinc;
    __syncthreads();
    if (w == 0 && lane < 8) {
        int x = wsum[lane];
        #pragma unroll
        for (int o = 1; o < 8; o <<= 1) {
            int t2 = __shfl_up_sync(0xffu, x, o);
            if (lane >= o) x += t2;
        }
        wsum[lane] = x;
    }
    __syncthreads();
    int base = (vinc - s) + (w > 0 ? wsum[w - 1] : 0);
    #pragma unroll
    for (int i = 0; i < 8; i++) {
        int st = base + loc[i];
        g_start[tid * 8 + i] = st;
        g_cursor[tid * 8 + i] = st;
    }
    if (tid == 255) g_start[NA] = E_;
}

// ---------------- 9: scatter edges into u-buckets ----------------
__global__ void k_scatter(const int* __restrict__ u) {
    int e = blockIdx.x * 256 + threadIdx.x;
    int p = atomicAdd(&g_cursor[u[e]], 1);
    g_perm[p] = e;
}

// ---------------- 10: A' GEMM (x<256) + C init (x>=256) ----------------
__global__ void __launch_bounds__(256)
k_agemm(const float* __restrict__ W, const float* __restrict__ V,
        const float* __restrict__ Bb) {
    __shared__ float4 hsr4[16][8];            // 2 KB, used by both branches
    if (blockIdx.x < 256) {
        int rh = blockIdx.x;
        int jj = threadIdx.x & 31, ar = threadIdx.x >> 5;   // ar 0..7
        u64 w2[16];
        #pragma unroll
        for (int k = 0; k < 16; k++) {
            float wl = W[rh * 1024 + (2*k)   * 32 + jj];
            float wh = W[rh * 1024 + (2*k+1) * 32 + jj];
            unsigned lo = __float_as_uint(wl), hi = __float_as_uint(wh);
            w2[k] = ((u64)hi << 32) | lo;
        }
        float v2c = V[rh * 64 + 32 + jj];
        int a0beg = blockIdx.y * (NA / 2);
        for (int a0 = a0beg; a0 < a0beg + NA / 2; a0 += 16) {
            int t = threadIdx.x;
            ((float*)hsr4)[t]       = g_hsT[a0 * NINP + t];
            ((float*)hsr4)[t + 256] = g_hsT[a0 * NINP + t + 256];
            __syncthreads();
            const u64* hA = (const u64*)hsr4[ar];
            const u64* hB = (const u64*)hsr4[ar + 8];
            u64 pa0 = 0, pa1 = 0, pb0 = 0, pb1 = 0;
            #pragma unroll
            for (int k = 0; k < 16; k += 2) {
                pa0 = ffma2(w2[k+0], hA[k+0], pa0);
                pa1 = ffma2(w2[k+1], hA[k+1], pa1);
                pb0 = ffma2(w2[k+0], hB[k+0], pb0);
                pb1 = ffma2(w2[k+1], hB[k+1], pb1);
            }
            g_Ap[(size_t)(a0 + ar)     * 8192 + rh * 32 + jj] = v2c + hsum2(pa0) + hsum2(pa1);
            g_Ap[(size_t)(a0 + ar + 8) * 8192 + rh * 32 + jj] = v2c + hsum2(pb0) + hsum2(pb1);
            __syncthreads();
        }
    } else {
        // C init: unit covers 16 a-rows
        int unit = (blockIdx.x - 256) + blockIdx.y * 64;    // 0..127
        int a0 = unit * 16;
        int rh = threadIdx.x;
        u64 v1r[16];
        const u64* vp = (const u64*)(V + rh * 64);
        #pragma unroll
        for (int q = 0; q < 16; q++) v1r[q] = vp[q];
        float bb = Bb[rh];
        float* hsm2 = (float*)hsr4;
        hsm2[rh]       = g_hsT[a0 * NINP + rh];
        hsm2[rh + 256] = g_hsT[a0 * NINP + rh + 256];
        __syncthreads();
        #pragma unroll
        for (int i = 0; i < 16; i++) {
            const u64* h2 = (const u64*)(hsm2 + i * 32);
            u64 acc0 = 0, acc1 = 0;
            #pragma unroll
            for (int q = 0; q < 16; q += 2) {
                acc0 = ffma2(v1r[q+0], h2[q+0], acc0);
                acc1 = ffma2(v1r[q+1], h2[q+1], acc1);
            }
            g_C[(a0 + i) * NRH + rh] = bb + hsum2(acc0) + hsum2(acc1);
        }
    }
}

// ---------------- 11: per-edge dot; z[e,rh]; running z-stats ----------------
__global__ void __launch_bounds__(256)
k_edge(const int* __restrict__ v) {
    int a  = blockIdx.x;                      // u-bucket
    int rh = threadIdx.x;
    u64 areg[16];
    const u64* ap = (const u64*)(g_Ap + (size_t)a * 8192 + rh * 32);
    #pragma unroll
    for (int q = 0; q < 16; q++) areg[q] = ap[q];
    float cinit = g_C[a * NRH + rh];
    int s = g_start[a], eend = g_start[a + 1];
    float s1 = 0.f, s2 = 0.f;
    __shared__ float4 hts4[8][8];
    __shared__ int eid[8];
    for (int p0 = s; p0 < eend; p0 += 8) {
        int nb = min(8, eend - p0);
        if (rh < nb * 32) {
            int g = rh >> 5, lj = rh & 31;
            int e = g_perm[p0 + g];
            if (lj == 0) eid[g] = e;
            ((float*)hts4[g])[lj] = g_htT[v[e] * NINP + lj];
        }
        __syncthreads();
        for (int q = 0; q < nb; q++) {
            const u64* hp = (const u64*)hts4[q];
            u64 p0a = 0, p1a = 0;
            #pragma unroll
            for (int i = 0; i < 16; i += 2) {
                p0a = ffma2(areg[i+0], hp[i+0], p0a);
                p1a = ffma2(areg[i+1], hp[i+1], p1a);
            }
            float acc = cinit + hsum2(p0a) + hsum2(p1a);
            g_z[(size_t)eid[q] * NRH + rh] = acc;
            s1 += acc; s2 += acc * acc;
        }
        __syncthreads();
    }
    if (eend > s) {
        atomicAdd(&g_zsum[rh], s1);
        atomicAdd(&g_zsq[rh],  s2);
    }
}

// ---------------- 12: warp-per-edge tanh + reduce (zstats fused) ------------
__global__ void __launch_bounds__(256)
k_final(const float* __restrict__ gg, const float* __restrict__ be,
        const float* __restrict__ uu, float* __restrict__ out) {
    __shared__ float ssc[256], sof[256], su[256];
    int tid = threadIdx.x;
    {   // fused z layernorm params (deterministic, recomputed per CTA)
        float mu  = g_zsum[tid] * (1.0f / E_);
        float var = g_zsq[tid] * (1.0f / E_) - mu * mu;
        float sc  = gg[tid] * rsqrtf(var + 1e-5f);
        ssc[tid] = sc;
        sof[tid] = be[tid] - sc * mu;
        su[tid]  = uu[tid];
    }
    __syncthreads();
    int w = tid >> 5, l = tid & 31;
    int rh0 = l * 8;
    float sc0 = ssc[rh0+0], sc1 = ssc[rh0+1], sc2 = ssc[rh0+2], sc3 = ssc[rh0+3];
    float sc4 = ssc[rh0+4], sc5 = ssc[rh0+5], sc6 = ssc[rh0+6], sc7 = ssc[rh0+7];
    float of0 = sof[rh0+0], of1 = sof[rh0+1], of2 = sof[rh0+2], of3 = sof[rh0+3];
    float of4 = sof[rh0+4], of5 = sof[rh0+5], of6 = sof[rh0+6], of7 = sof[rh0+7];
    float u0 = su[rh0+0], u1 = su[rh0+1], u2 = su[rh0+2], u3 = su[rh0+3];
    float u4 = su[rh0+4], u5 = su[rh0+5], u6 = su[rh0+6], u7 = su[rh0+7];
    int e0 = blockIdx.x * 64 + w * 8;
    #pragma unroll
    for (int i = 0; i < 8; i++) {
        int e = e0 + i;
        const float4* zp = (const float4*)(g_z + (size_t)e * NRH) + l * 2;
        float4 za = zp[0], zb = zp[1];
        float s =  u0 * tanha(fmaf(sc0, za.x, of0));
        s += u1 * tanha(fmaf(sc1, za.y, of1));
        s += u2 * tanha(fmaf(sc2, za.z, of2));
        s += u3 * tanha(fmaf(sc3, za.w, of3));
        s += u4 * tanha(fmaf(sc4, zb.x, of4));
        s += u5 * tanha(fmaf(sc5, zb.y, of5));
        s += u6 * tanha(fmaf(sc6, zb.z, of6));
        s += u7 * tanha(fmaf(sc7, zb.w, of7));
        s += __shfl_xor_sync(0xffffffffu, s, 1);
        if ((l & 1) == 0) out[(size_t)e * 16 + (l >> 1)] = s;
    }
}

// ---------------- launch ----------------
extern "C" void kernel_launch(void* const* d_in, const int* in_sizes, int n_in,
                              void* d_out, int out_size) {
    const int*   seq  = (const int*)d_in[0];
    const int*   p2g  = (const int*)d_in[1];
    const int*   idx  = (const int*)d_in[2];
    const int*   u    = (const int*)d_in[3];
    const int*   v    = (const int*)d_in[4];
    const float* emb  = (const float*)d_in[5];
    const float* wihF = (const float*)d_in[6];
    const float* whhF = (const float*)d_in[7];
    const float* bihF = (const float*)d_in[8];
    const float* bhhF = (const float*)d_in[9];
    const float* wihB = (const float*)d_in[10];
    const float* whhB = (const float*)d_in[11];
    const float* bihB = (const float*)d_in[12];
    const float* bhhB = (const float*)d_in[13];
    const float* wS   = (const float*)d_in[14];
    const float* bS   = (const float*)d_in[15];
    const float* wD   = (const float*)d_in[16];
    const float* bD   = (const float*)d_in[17];
    const float* gS   = (const float*)d_in[18];
    const float* beS  = (const float*)d_in[19];
    const float* gD   = (const float*)d_in[20];
    const float* beD  = (const float*)d_in[21];
    const float* ntlW = (const float*)d_in[22];
    const float* ntlV = (const float*)d_in[23];
    const float* ntlB = (const float*)d_in[24];
    const float* ntlU = (const float*)d_in[25];
    const float* ntlG = (const float*)d_in[26];
    const float* ntlBe= (const float*)d_in[27];
    float* out = (float*)d_out;

    k_init     <<<8, 256>>>();
    k_embed    <<<64, 256>>>(seq, p2g, emb, u, v);
    k_xproj    <<<128, 256>>>(wihF, bihF, bhhF, wihB, bihB, bhhB);
    k_lstm     <<<128, 256>>>(whhF, whhB);
    k_nodeproj <<<2048, 64>>>(p2g, idx, wS, bS, wD, bD);
    k_bnstats  <<<64, 256>>>();
    k_bnnorm   <<<512, 256>>>(gS, beS, gD, beD);
    k_scan     <<<1, 256>>>();
    k_scatter  <<<256, 256>>>(u);
    k_agemm    <<<dim3(320, 2), 256>>>(ntlW, ntlV, ntlB);
    k_edge     <<<2048, 256>>>(v);
    k_final    <<<1024, 256>>>(ntlG, ntlBe, ntlU, out);
}

// round 9
// speedup vs baseline: 1.2508x; 1.0269x over previous
#include <cuda_runtime.h>
#include <cuda_bf16.h>

// ---------------- problem constants ----------------
#define B_    64
#define L_    512
#define G_    128
#define N_    32
#define K_    8
#define E_    65536
#define DTOK  64
#define H_    64
#define NINP  32
#define NRH   256          // NREL*NHID = 16*16
#define NA    2048         // B*N

typedef unsigned long long u64;

// ---------------- scratch (__device__ globals; no allocation) ----------------
__device__ float g_xgrp[B_*G_*DTOK];        // (B,G,64)
__device__ float g_hgrp[B_*G_*2*H_];        // (B,G,128)  fwd[0:64) bwd[64:128)
__device__ float g_rawS[NA*NINP];
__device__ float g_rawD[NA*NINP];
__device__ float g_hsT [NA*NINP];
__device__ float g_htT [NA*NINP];
__device__ int   g_cntU[NA];
__device__ int   g_cntV[NA];
__device__ int   g_start[NA+1];
__device__ int   g_cursor[NA];
__device__ int   g_perm[E_];
__device__ float g_bnMu[64];
__device__ float g_bnInv[64];
__device__ float g_Ap[(size_t)NA*NRH*32];   // 64 MB
__device__ float g_C [NA*NRH];
__device__ float g_zsum[NRH];
__device__ float g_zsq [NRH];
__device__ float g_z[(size_t)E_*NRH];       // 64 MB, layout (E, 256)

// ---------------- math helpers ----------------
__device__ __forceinline__ float tanha(float x) {           // MUFU.TANH
    float y; asm("tanh.approx.f32 %0, %1;" : "=f"(y) : "f"(x)); return y;
}
__device__ __forceinline__ float siga(float x) {            // exact identity
    return fmaf(0.5f, tanha(0.5f * x), 0.5f);
}
__device__ __forceinline__ u64 ffma2(u64 a, u64 b, u64 c) { // packed f32x2 FMA
    u64 d; asm("fma.rn.f32x2 %0, %1, %2, %3;" : "=l"(d) : "l"(a), "l"(b), "l"(c));
    return d;
}
__device__ __forceinline__ float hsum2(u64 x) {
    return __uint_as_float((unsigned)(x & 0xffffffffull)) +
           __uint_as_float((unsigned)(x >> 32));
}
__device__ __forceinline__ void lds128(u64& lo, u64& hi, unsigned addr) {
    asm volatile("ld.shared.v2.u64 {%0,%1},[%2];" : "=l"(lo), "=l"(hi) : "r"(addr));
}

// ---------------- 1: token embed + scatter-sum; zero edge counters ----------
__global__ void k_embed(const int* __restrict__ seq, const int* __restrict__ p2g,
                        const float* __restrict__ emb) {
    __shared__ float acc[G_ * DTOK];          // 32 KB
    int b = blockIdx.x;
    int tid = threadIdx.x;                    // 256
    if (tid < 32) { g_cntU[b * 32 + tid] = 0; g_cntV[b * 32 + tid] = 0; }
    for (int i = tid; i < G_ * DTOK; i += 256) acc[i] = 0.f;
    __syncthreads();
    int sub  = tid & 15;                      // 16 threads per token (float4 each)
    int tok0 = tid >> 4;
    for (int l = tok0; l < L_; l += 16) {
        int s = seq[b * L_ + l];
        int g = p2g[b * L_ + l];
        float4 x4 = ((const float4*)(emb + (size_t)s * DTOK))[sub];
        float* dst = acc + g * DTOK + sub * 4;
        atomicAdd(dst + 0, x4.x); atomicAdd(dst + 1, x4.y);
        atomicAdd(dst + 2, x4.z); atomicAdd(dst + 3, x4.w);
    }
    __syncthreads();
    for (int i = tid; i < G_ * DTOK; i += 256) g_xgrp[b * G_ * DTOK + i] = acc[i];
}

// ---------------- 2: fused BiLSTM (input proj + recurrence in one) ----------
// thread j handles row r = (j&3)*64 + (j>>2): gate (j&3) of h-index (j>>2).
// gates of index i land contiguously at gsm[4i..4i+3] -> one LDS.128 in phase 2.
__global__ void __launch_bounds__(256, 1)
k_lstm(const float* __restrict__ wihF, const float* __restrict__ whhF,
       const float* __restrict__ bihF, const float* __restrict__ bhhF,
       const float* __restrict__ wihB, const float* __restrict__ whhB,
       const float* __restrict__ bihB, const float* __restrict__ bhhB) {
    int bid = blockIdx.x;                      // 0..127
    int b   = bid & 63;
    int dir = bid >> 6;
    const float* wih = dir ? wihB : wihF;
    const float* whh = dir ? whhB : whhF;
    const float* bih = dir ? bihB : bihF;
    const float* bhh = dir ? bhhB : bhhF;
    int j    = threadIdx.x;
    int gate = j & 3;
    int idx  = j >> 2;
    int r    = gate * 64 + idx;                // original gate-row

    __shared__ float xsm[G_ * DTOK];           // 32 KB: all 128 timesteps
    __shared__ float hsm[H_];                  // current h
    __shared__ float gsm[256];                 // activated gates, [4i+g] layout

    // stage all x for this sequence
    {
        const float4* src = (const float4*)(g_xgrp + b * G_ * DTOK);
        float4* xd = (float4*)xsm;
        #pragma unroll
        for (int i = 0; i < 8; i++) xd[j + i * 256] = src[j + i * 256];
    }

    u64 wi2[32], wh2[32];
    const u64* wip = (const u64*)(wih + r * DTOK);
    const u64* whp = (const u64*)(whh + r * H_);
    #pragma unroll
    for (int k = 0; k < 32; k++) { wi2[k] = wip[k]; wh2[k] = whp[k]; }
    float bias = bih[r] + bhh[r];
    float c = 0.f;
    if (j < 64) hsm[j] = 0.f;
    __syncthreads();

    unsigned hbase = (unsigned)__cvta_generic_to_shared(hsm);
    unsigned xall  = (unsigned)__cvta_generic_to_shared(xsm);

    for (int t = 0; t < G_; t++) {
        int tg = dir ? (G_ - 1 - t) : t;
        unsigned xbase = xall + tg * (DTOK * 4);
        u64 ax0 = 0, ax1 = 0, ax2 = 0, ax3 = 0;
        u64 ah0 = 0, ah1 = 0, ah2 = 0, ah3 = 0;
        #pragma unroll
        for (int k = 0; k < 16; k += 2) {
            u64 x0, x1, x2, x3, h0, h1, h2, h3;
            lds128(x0, x1, xbase + k * 16);
            lds128(x2, x3, xbase + k * 16 + 16);
            lds128(h0, h1, hbase + k * 16);
            lds128(h2, h3, hbase + k * 16 + 16);
            ax0 = ffma2(wi2[2*k+0], x0, ax0);
            ax1 = ffma2(wi2[2*k+1], x1, ax1);
            ax2 = ffma2(wi2[2*k+2], x2, ax2);
            ax3 = ffma2(wi2[2*k+3], x3, ax3);
            ah0 = ffma2(wh2[2*k+0], h0, ah0);
            ah1 = ffma2(wh2[2*k+1], h1, ah1);
            ah2 = ffma2(wh2[2*k+2], h2, ah2);
            ah3 = ffma2(wh2[2*k+3], h3, ah3);
        }
        float pre = bias
            + ((hsum2(ax0) + hsum2(ax1)) + (hsum2(ax2) + hsum2(ax3)))
            + ((hsum2(ah0) + hsum2(ah1)) + (hsum2(ah2) + hsum2(ah3)));
        gsm[j] = (gate == 2) ? tanha(pre) : siga(pre);
        __syncthreads();
        if (gate == 0) {
            float4 g4 = *(const float4*)(gsm + 4 * idx);   // i,f,g,o
            c = fmaf(g4.y, c, g4.x * g4.z);
            float h = g4.w * tanha(c);
            hsm[idx] = h;
            g_hgrp[(b * G_ + tg) * (2 * H_) + dir * H_ + idx] = h;
        }
        __syncthreads();
    }
}

// ---------------- 3: node gather + projections; fused edge histograms -------
__global__ void __launch_bounds__(256)
k_nodeproj(const int* __restrict__ p2g, const int* __restrict__ idx,
           const int* __restrict__ u, const int* __restrict__ v,
           const float* __restrict__ wS, const float* __restrict__ bS,
           const float* __restrict__ wD, const float* __restrict__ bD) {
    int tid = threadIdx.x;
    // fused histograms: 128 edges per CTA (counters zeroed by k_embed)
    if (tid < 128) {
        int e = blockIdx.x * 128 + tid;
        atomicAdd(&g_cntU[u[e]], 1);
        atomicAdd(&g_cntV[v[e]], 1);
    }
    int grp = tid >> 6, lt = tid & 63;
    int a = blockIdx.x * 4 + grp;             // node 0..2047
    int b = a >> 5, n = a & 31;
    __shared__ float hrow[4][2 * H_];
    float s0 = 0.f, s1 = 0.f;
    #pragma unroll
    for (int k = 0; k < K_; k++) {
        int pos = idx[(b * N_ + n) * K_ + k];
        int g   = p2g[b * L_ + pos];
        const float* hp = g_hgrp + (b * G_ + g) * (2 * H_);
        s0 += hp[lt]; s1 += hp[lt + 64];
    }
    hrow[grp][lt] = s0; hrow[grp][lt + 64] = s1;
    __syncthreads();
    const float* w = (lt < 32) ? (wS + lt * 128) : (wD + (lt - 32) * 128);
    float bb = (lt < 32) ? bS[lt] : bD[lt - 32];
    const u64* h2 = (const u64*)hrow[grp];
    const u64* w2 = (const u64*)w;
    u64 a0 = 0, a1 = 0, a2 = 0, a3 = 0;
    #pragma unroll
    for (int q = 0; q < 64; q += 4) {
        a0 = ffma2(w2[q+0], h2[q+0], a0);
        a1 = ffma2(w2[q+1], h2[q+1], a1);
        a2 = ffma2(w2[q+2], h2[q+2], a2);
        a3 = ffma2(w2[q+3], h2[q+3], a3);
    }
    float acc = bb + (hsum2(a0) + hsum2(a1)) + (hsum2(a2) + hsum2(a3));
    if (lt < 32) g_rawS[a * NINP + lt] = acc;
    else         g_rawD[a * NINP + lt - 32] = acc;
}

// ---------------- 4: BN stats (CTAs 0-63) + scan + zsum zero (CTA 64) -------
__global__ void k_bnstats() {
    int c = blockIdx.x;
    int tid = threadIdx.x;
    if (c == 64) {
        // zero z accumulators (consumed by k_edge, later launch)
        g_zsum[tid] = 0.f; g_zsq[tid] = 0.f;
        // parallel exclusive scan of u-histogram -> start/cursor
        int lane = tid & 31, w = tid >> 5;
        int loc[8]; int s = 0;
        #pragma unroll
        for (int i = 0; i < 8; i++) { loc[i] = s; s += g_cntU[tid * 8 + i]; }
        int vinc = s;
        #pragma unroll
        for (int o = 1; o < 32; o <<= 1) {
            int t2 = __shfl_up_sync(0xffffffffu, vinc, o);
            if (lane >= o) vinc += t2;
        }
        __shared__ int wsum[8];
        if (lane == 31) wsum[w] = vinc;
        __syncthreads();
        if (w == 0 && lane < 8) {
            int x = wsum[lane];
            #pragma unroll
            for (int o = 1; o < 8; o <<= 1) {
                int t2 = __shfl_up_sync(0xffu, x, o);
                if (lane >= o) x += t2;
            }
            wsum[lane] = x;
        }
        __syncthreads();
        int base = (vinc - s) + (w > 0 ? wsum[w - 1] : 0);
        #pragma unroll
        for (int i = 0; i < 8; i++) {
            int st = base + loc[i];
            g_start[tid * 8 + i] = st;
            g_cursor[tid * 8 + i] = st;
        }
        if (tid == 255) g_start[NA] = E_;
        return;
    }
    const float* raw = (c < 32) ? g_rawS : g_rawD;
    const int*   cnt = (c < 32) ? g_cntU : g_cntV;
    int cc = c & 31;
    float s = 0.f, s2 = 0.f;
    for (int a = tid; a < NA; a += 256) {
        float w = (float)cnt[a];
        float x = raw[a * NINP + cc];
        s += w * x; s2 += w * x * x;
    }
    __shared__ float r1[256], r2[256];
    r1[tid] = s; r2[tid] = s2; __syncthreads();
    for (int o = 128; o > 0; o >>= 1) {
        if (tid < o) { r1[tid] += r1[tid + o]; r2[tid] += r2[tid + o]; }
        __syncthreads();
    }
    if (tid == 0) {
        float mu  = r1[0] * (1.0f / E_);
        float var = r2[0] * (1.0f / E_) - mu * mu;
        g_bnMu[c] = mu;
        g_bnInv[c] = rsqrtf(var + 1e-5f);
    }
}

// ---------------- 5: scatter (CTAs 0-255) + bn normalize (CTAs 256-767) -----
__global__ void k_scatnorm(const int* __restrict__ u,
                           const float* __restrict__ gS, const float* __restrict__ beS,
                           const float* __restrict__ gD, const float* __restrict__ beD) {
    int x = blockIdx.x, tid = threadIdx.x;
    if (x < 256) {
        int e = x * 256 + tid;
        int p = atomicAdd(&g_cursor[u[e]], 1);
        g_perm[p] = e;
    } else {
        int t = (x - 256) * 256 + tid;        // 512*256 = 2048*64
        int a = t >> 6, c = t & 63;
        int cc = c & 31;
        if (c < 32) {
            float xv = g_rawS[a * NINP + cc];
            g_hsT[a * NINP + cc] = gS[cc] * (xv - g_bnMu[c]) * g_bnInv[c] + beS[cc];
        } else {
            float xv = g_rawD[a * NINP + cc];
            g_htT[a * NINP + cc] = gD[cc] * (xv - g_bnMu[c]) * g_bnInv[c] + beD[cc];
        }
    }
}

// ---------------- 6: A' GEMM (x<256) + C init (x>=256) ----------------
__global__ void __launch_bounds__(256)
k_agemm(const float* __restrict__ W, const float* __restrict__ V,
        const float* __restrict__ Bb) {
    __shared__ float4 hsr4[16][8];            // 2 KB, used by both branches
    if (blockIdx.x < 256) {
        int rh = blockIdx.x;
        int jj = threadIdx.x & 31, ar = threadIdx.x >> 5;   // ar 0..7
        u64 w2[16];
        #pragma unroll
        for (int k = 0; k < 16; k++) {
            float wl = W[rh * 1024 + (2*k)   * 32 + jj];
            float wh = W[rh * 1024 + (2*k+1) * 32 + jj];
            unsigned lo = __float_as_uint(wl), hi = __float_as_uint(wh);
            w2[k] = ((u64)hi << 32) | lo;
        }
        float v2c = V[rh * 64 + 32 + jj];
        int a0beg = blockIdx.y * (NA / 2);
        for (int a0 = a0beg; a0 < a0beg + NA / 2; a0 += 16) {
            int t = threadIdx.x;
            ((float*)hsr4)[t]       = g_hsT[a0 * NINP + t];
            ((float*)hsr4)[t + 256] = g_hsT[a0 * NINP + t + 256];
            __syncthreads();
            const u64* hA = (const u64*)hsr4[ar];
            const u64* hB = (const u64*)hsr4[ar + 8];
            u64 pa0 = 0, pa1 = 0, pb0 = 0, pb1 = 0;
            #pragma unroll
            for (int k = 0; k < 16; k += 2) {
                pa0 = ffma2(w2[k+0], hA[k+0], pa0);
                pa1 = ffma2(w2[k+1], hA[k+1], pa1);
                pb0 = ffma2(w2[k+0], hB[k+0], pb0);
                pb1 = ffma2(w2[k+1], hB[k+1], pb1);
            }
            g_Ap[(size_t)(a0 + ar)     * 8192 + rh * 32 + jj] = v2c + hsum2(pa0) + hsum2(pa1);
            g_Ap[(size_t)(a0 + ar + 8) * 8192 + rh * 32 + jj] = v2c + hsum2(pb0) + hsum2(pb1);
            __syncthreads();
        }
    } else {
        int unit = (blockIdx.x - 256) + blockIdx.y * 64;    // 0..127
        int a0 = unit * 16;
        int rh = threadIdx.x;
        u64 v1r[16];
        const u64* vp = (const u64*)(V + rh * 64);
        #pragma unroll
        for (int q = 0; q < 16; q++) v1r[q] = vp[q];
        float bb = Bb[rh];
        float* hsm2 = (float*)hsr4;
        hsm2[rh]       = g_hsT[a0 * NINP + rh];
        hsm2[rh + 256] = g_hsT[a0 * NINP + rh + 256];
        __syncthreads();
        #pragma unroll
        for (int i = 0; i < 16; i++) {
            const u64* h2 = (const u64*)(hsm2 + i * 32);
            u64 acc0 = 0, acc1 = 0;
            #pragma unroll
            for (int q = 0; q < 16; q += 2) {
                acc0 = ffma2(v1r[q+0], h2[q+0], acc0);
                acc1 = ffma2(v1r[q+1], h2[q+1], acc1);
            }
            g_C[(a0 + i) * NRH + rh] = bb + hsum2(acc0) + hsum2(acc1);
        }
    }
}

// ---------------- 7: per-edge dot; z[e,rh]; running z-stats -----------------
__global__ void __launch_bounds__(256)
k_edge(const int* __restrict__ v) {
    int a  = blockIdx.x;                      // u-bucket
    int rh = threadIdx.x;
    u64 areg[16];
    const u64* ap = (const u64*)(g_Ap + (size_t)a * 8192 + rh * 32);
    #pragma unroll
    for (int q = 0; q < 16; q++) areg[q] = ap[q];
    float cinit = g_C[a * NRH + rh];
    int s = g_start[a], eend = g_start[a + 1];
    float s1 = 0.f, s2 = 0.f;
    __shared__ float hts[16][32];
    __shared__ int eid[16];
    for (int p0 = s; p0 < eend; p0 += 16) {
        int nb = min(16, eend - p0);
        #pragma unroll
        for (int base = 0; base < 512; base += 256) {
            int flat = base + rh;
            int g = flat >> 5, lj = flat & 31;
            if (g < nb) {
                int e = g_perm[p0 + g];
                if (lj == 0) eid[g] = e;
                hts[g][lj] = g_htT[v[e] * NINP + lj];
            }
        }
        __syncthreads();
        for (int q = 0; q < nb; q++) {
            const u64* hp = (const u64*)hts[q];
            u64 p0a = 0, p1a = 0;
            #pragma unroll
            for (int i = 0; i < 16; i += 2) {
                p0a = ffma2(areg[i+0], hp[i+0], p0a);
                p1a = ffma2(areg[i+1], hp[i+1], p1a);
            }
            float acc = cinit + hsum2(p0a) + hsum2(p1a);
            g_z[(size_t)eid[q] * NRH + rh] = acc;
            s1 += acc; s2 += acc * acc;
        }
        __syncthreads();
    }
    if (eend > s) {
        atomicAdd(&g_zsum[rh], s1);
        atomicAdd(&g_zsq[rh],  s2);
    }
}

// ---------------- 8: warp-per-edge tanh + reduce (zstats fused) -------------
__global__ void __launch_bounds__(256)
k_final(const float* __restrict__ gg, const float* __restrict__ be,
        const float* __restrict__ uu, float* __restrict__ out) {
    __shared__ float ssc[256], sof[256], su[256];
    int tid = threadIdx.x;
    {   // fused z layernorm params (deterministic, recomputed per CTA)
        float mu  = g_zsum[tid] * (1.0f / E_);
        float var = g_zsq[tid] * (1.0f / E_) - mu * mu;
        float sc  = gg[tid] * rsqrtf(var + 1e-5f);
        ssc[tid] = sc;
        sof[tid] = be[tid] - sc * mu;
        su[tid]  = uu[tid];
    }
    __syncthreads();
    int w = tid >> 5, l = tid & 31;
    int rh0 = l * 8;
    float sc0 = ssc[rh0+0], sc1 = ssc[rh0+1], sc2 = ssc[rh0+2], sc3 = ssc[rh0+3];
    float sc4 = ssc[rh0+4], sc5 = ssc[rh0+5], sc6 = ssc[rh0+6], sc7 = ssc[rh0+7];
    float of0 = sof[rh0+0], of1 = sof[rh0+1], of2 = sof[rh0+2], of3 = sof[rh0+3];
    float of4 = sof[rh0+4], of5 = sof[rh0+5], of6 = sof[rh0+6], of7 = sof[rh0+7];
    float u0 = su[rh0+0], u1 = su[rh0+1], u2 = su[rh0+2], u3 = su[rh0+3];
    float u4 = su[rh0+4], u5 = su[rh0+5], u6 = su[rh0+6], u7 = su[rh0+7];
    int e0 = blockIdx.x * 64 + w * 8;
    #pragma unroll
    for (int i = 0; i < 8; i++) {
        int e = e0 + i;
        const float4* zp = (const float4*)(g_z + (size_t)e * NRH) + l * 2;
        float4 za = zp[0], zb = zp[1];
        float s =  u0 * tanha(fmaf(sc0, za.x, of0));
        s += u1 * tanha(fmaf(sc1, za.y, of1));
        s += u2 * tanha(fmaf(sc2, za.z, of2));
        s += u3 * tanha(fmaf(sc3, za.w, of3));
        s += u4 * tanha(fmaf(sc4, zb.x, of4));
        s += u5 * tanha(fmaf(sc5, zb.y, of5));
        s += u6 * tanha(fmaf(sc6, zb.z, of6));
        s += u7 * tanha(fmaf(sc7, zb.w, of7));
        s += __shfl_xor_sync(0xffffffffu, s, 1);
        if ((l & 1) == 0) out[(size_t)e * 16 + (l >> 1)] = s;
    }
}

// ---------------- launch ----------------
extern "C" void kernel_launch(void* const* d_in, const int* in_sizes, int n_in,
                              void* d_out, int out_size) {
    const int*   seq  = (const int*)d_in[0];
    const int*   p2g  = (const int*)d_in[1];
    const int*   idx  = (const int*)d_in[2];
    const int*   u    = (const int*)d_in[3];
    const int*   v    = (const int*)d_in[4];
    const float* emb  = (const float*)d_in[5];
    const float* wihF = (const float*)d_in[6];
    const float* whhF = (const float*)d_in[7];
    const float* bihF = (const float*)d_in[8];
    const float* bhhF = (const float*)d_in[9];
    const float* wihB = (const float*)d_in[10];
    const float* whhB = (const float*)d_in[11];
    const float* bihB = (const float*)d_in[12];
    const float* bhhB = (const float*)d_in[13];
    const float* wS   = (const float*)d_in[14];
    const float* bS   = (const float*)d_in[15];
    const float* wD   = (const float*)d_in[16];
    const float* bD   = (const float*)d_in[17];
    const float* gS   = (const float*)d_in[18];
    const float* beS  = (const float*)d_in[19];
    const float* gD   = (const float*)d_in[20];
    const float* beD  = (const float*)d_in[21];
    const float* ntlW = (const float*)d_in[22];
    const float* ntlV = (const float*)d_in[23];
    const float* ntlB = (const float*)d_in[24];
    const float* ntlU = (const float*)d_in[25];
    const float* ntlG = (const float*)d_in[26];
    const float* ntlBe= (const float*)d_in[27];
    float* out = (float*)d_out;

    k_embed    <<<64, 256>>>(seq, p2g, emb);
    k_lstm     <<<128, 256>>>(wihF, whhF, bihF, bhhF, wihB, whhB, bihB, bhhB);
    k_nodeproj <<<512, 256>>>(p2g, idx, u, v, wS, bS, wD, bD);
    k_bnstats  <<<65, 256>>>();
    k_scatnorm <<<768, 256>>>(u, gS, beS, gD, beD);
    k_agemm    <<<dim3(320, 2), 256>>>(ntlW, ntlV, ntlB);
    k_edge     <<<2048, 256>>>(v);
    k_final    <<<1024, 256>>>(ntlG, ntlBe, ntlU, out);
}

// round 10
// speedup vs baseline: 1.2606x; 1.0078x over previous
#include <cuda_runtime.h>
#include <cuda_bf16.h>

// ---------------- problem constants ----------------
#define B_    64
#define L_    512
#define G_    128
#define N_    32
#define K_    8
#define E_    65536
#define DTOK  64
#define H_    64
#define NINP  32
#define NRH   256          // NREL*NHID = 16*16
#define NA    2048         // B*N

typedef unsigned long long u64;

// ---------------- scratch (__device__ globals; no allocation) ----------------
__device__ float g_xgrp[B_*G_*DTOK];        // (B,G,64)
__device__ float g_hgrp[B_*G_*2*H_];        // (B,G,128)  fwd[0:64) bwd[64:128)
__device__ float g_rawS[NA*NINP];
__device__ float g_rawD[NA*NINP];
__device__ float g_hsT [NA*NINP];
__device__ float g_htT [NA*NINP];
__device__ int   g_cntU[NA];
__device__ int   g_cntV[NA];
__device__ int   g_start[NA+1];
__device__ int   g_cursor[NA];
__device__ int   g_perm[E_];
__device__ float g_bnMu[64];
__device__ float g_bnInv[64];
__device__ float g_Ap[(size_t)NA*NRH*32];   // 64 MB
__device__ float g_C [NA*NRH];
__device__ float g_zsum[NRH];
__device__ float g_zsq [NRH];
__device__ float g_z[(size_t)E_*NRH];       // 64 MB, layout (E, 256)

// ---------------- math helpers ----------------
__device__ __forceinline__ float tanha(float x) {           // MUFU.TANH
    float y; asm("tanh.approx.f32 %0, %1;" : "=f"(y) : "f"(x)); return y;
}
__device__ __forceinline__ float siga(float x) {            // exact identity
    return fmaf(0.5f, tanha(0.5f * x), 0.5f);
}
__device__ __forceinline__ u64 ffma2(u64 a, u64 b, u64 c) { // packed f32x2 FMA
    u64 d; asm("fma.rn.f32x2 %0, %1, %2, %3;" : "=l"(d) : "l"(a), "l"(b), "l"(c));
    return d;
}
__device__ __forceinline__ float hsum2(u64 x) {
    return __uint_as_float((unsigned)(x & 0xffffffffull)) +
           __uint_as_float((unsigned)(x >> 32));
}
__device__ __forceinline__ void lds128(u64& lo, u64& hi, unsigned addr) {
    asm volatile("ld.shared.v2.u64 {%0,%1},[%2];" : "=l"(lo), "=l"(hi) : "r"(addr));
}

// ---------------- 1: token embed + scatter-sum; zero edge counters ----------
__global__ void k_embed(const int* __restrict__ seq, const int* __restrict__ p2g,
                        const float* __restrict__ emb) {
    __shared__ float acc[G_ * DTOK];          // 32 KB
    int b = blockIdx.x;
    int tid = threadIdx.x;                    // 256
    if (tid < 32) { g_cntU[b * 32 + tid] = 0; g_cntV[b * 32 + tid] = 0; }
    for (int i = tid; i < G_ * DTOK; i += 256) acc[i] = 0.f;
    __syncthreads();
    int sub  = tid & 15;                      // 16 threads per token (float4 each)
    int tok0 = tid >> 4;
    for (int l = tok0; l < L_; l += 16) {
        int s = seq[b * L_ + l];
        int g = p2g[b * L_ + l];
        float4 x4 = ((const float4*)(emb + (size_t)s * DTOK))[sub];
        float* dst = acc + g * DTOK + sub * 4;
        atomicAdd(dst + 0, x4.x); atomicAdd(dst + 1, x4.y);
        atomicAdd(dst + 2, x4.z); atomicAdd(dst + 3, x4.w);
    }
    __syncthreads();
    for (int i = tid; i < G_ * DTOK; i += 256) g_xgrp[b * G_ * DTOK + i] = acc[i];
}

// ---------------- 2: fused BiLSTM (input proj + recurrence in one) ----------
// thread j handles row r = (j&3)*64 + (j>>2): gate (j&3) of h-index (j>>2).
// gates of index i land contiguously at gsm[4i..4i+3] -> one LDS.128 in phase 2.
__global__ void __launch_bounds__(256, 1)
k_lstm(const float* __restrict__ wihF, const float* __restrict__ whhF,
       const float* __restrict__ bihF, const float* __restrict__ bhhF,
       const float* __restrict__ wihB, const float* __restrict__ whhB,
       const float* __restrict__ bihB, const float* __restrict__ bhhB) {
    int bid = blockIdx.x;                      // 0..127
    int b   = bid & 63;
    int dir = bid >> 6;
    const float* wih = dir ? wihB : wihF;
    const float* whh = dir ? whhB : whhF;
    const float* bih = dir ? bihB : bihF;
    const float* bhh = dir ? bhhB : bhhF;
    int j    = threadIdx.x;
    int gate = j & 3;
    int idx  = j >> 2;
    int r    = gate * 64 + idx;                // original gate-row

    __shared__ float xsm[G_ * DTOK];           // 32 KB: all 128 timesteps
    __shared__ float hsm[H_];                  // current h
    __shared__ float gsm[256];                 // activated gates, [4i+g] layout

    // stage all x for this sequence
    {
        const float4* src = (const float4*)(g_xgrp + b * G_ * DTOK);
        float4* xd = (float4*)xsm;
        #pragma unroll
        for (int i = 0; i < 8; i++) xd[j + i * 256] = src[j + i * 256];
    }

    u64 wi2[32], wh2[32];
    const u64* wip = (const u64*)(wih + r * DTOK);
    const u64* whp = (const u64*)(whh + r * H_);
    #pragma unroll
    for (int k = 0; k < 32; k++) { wi2[k] = wip[k]; wh2[k] = whp[k]; }
    float bias = bih[r] + bhh[r];
    float c = 0.f;
    if (j < 64) hsm[j] = 0.f;
    __syncthreads();

    unsigned hbase = (unsigned)__cvta_generic_to_shared(hsm);
    unsigned xall  = (unsigned)__cvta_generic_to_shared(xsm);

    for (int t = 0; t < G_; t++) {
        int tg = dir ? (G_ - 1 - t) : t;
        unsigned xbase = xall + tg * (DTOK * 4);
        u64 ax0 = 0, ax1 = 0, ax2 = 0, ax3 = 0;
        u64 ah0 = 0, ah1 = 0, ah2 = 0, ah3 = 0;
        #pragma unroll
        for (int k = 0; k < 16; k += 2) {
            u64 x0, x1, x2, x3, h0, h1, h2, h3;
            lds128(x0, x1, xbase + k * 16);
            lds128(x2, x3, xbase + k * 16 + 16);
            lds128(h0, h1, hbase + k * 16);
            lds128(h2, h3, hbase + k * 16 + 16);
            ax0 = ffma2(wi2[2*k+0], x0, ax0);
            ax1 = ffma2(wi2[2*k+1], x1, ax1);
            ax2 = ffma2(wi2[2*k+2], x2, ax2);
            ax3 = ffma2(wi2[2*k+3], x3, ax3);
            ah0 = ffma2(wh2[2*k+0], h0, ah0);
            ah1 = ffma2(wh2[2*k+1], h1, ah1);
            ah2 = ffma2(wh2[2*k+2], h2, ah2);
            ah3 = ffma2(wh2[2*k+3], h3, ah3);
        }
        float pre = bias
            + ((hsum2(ax0) + hsum2(ax1)) + (hsum2(ax2) + hsum2(ax3)))
            + ((hsum2(ah0) + hsum2(ah1)) + (hsum2(ah2) + hsum2(ah3)));
        gsm[j] = (gate == 2) ? tanha(pre) : siga(pre);
        __syncthreads();
        if (gate == 0) {
            float4 g4 = *(const float4*)(gsm + 4 * idx);   // i,f,g,o
            c = fmaf(g4.y, c, g4.x * g4.z);
            float h = g4.w * tanha(c);
            hsm[idx] = h;
            g_hgrp[(b * G_ + tg) * (2 * H_) + dir * H_ + idx] = h;
        }
        __syncthreads();
    }
}

// ---------------- 3: node gather + projections; fused edge histograms -------
__global__ void __launch_bounds__(256)
k_nodeproj(const int* __restrict__ p2g, const int* __restrict__ idx,
           const int* __restrict__ u, const int* __restrict__ v,
           const float* __restrict__ wS, const float* __restrict__ bS,
           const float* __restrict__ wD, const float* __restrict__ bD) {
    int tid = threadIdx.x;
    // fused histograms: 128 edges per CTA (counters zeroed by k_embed)
    if (tid < 128) {
        int e = blockIdx.x * 128 + tid;
        atomicAdd(&g_cntU[u[e]], 1);
        atomicAdd(&g_cntV[v[e]], 1);
    }
    int grp = tid >> 6, lt = tid & 63;
    int a = blockIdx.x * 4 + grp;             // node 0..2047
    int b = a >> 5, n = a & 31;
    __shared__ float hrow[4][2 * H_];
    float s0 = 0.f, s1 = 0.f;
    #pragma unroll
    for (int k = 0; k < K_; k++) {
        int pos = idx[(b * N_ + n) * K_ + k];
        int g   = p2g[b * L_ + pos];
        const float* hp = g_hgrp + (b * G_ + g) * (2 * H_);
        s0 += hp[lt]; s1 += hp[lt + 64];
    }
    hrow[grp][lt] = s0; hrow[grp][lt + 64] = s1;
    __syncthreads();
    const float* w = (lt < 32) ? (wS + lt * 128) : (wD + (lt - 32) * 128);
    float bb = (lt < 32) ? bS[lt] : bD[lt - 32];
    const u64* h2 = (const u64*)hrow[grp];
    const u64* w2 = (const u64*)w;
    u64 a0 = 0, a1 = 0, a2 = 0, a3 = 0;
    #pragma unroll
    for (int q = 0; q < 64; q += 4) {
        a0 = ffma2(w2[q+0], h2[q+0], a0);
        a1 = ffma2(w2[q+1], h2[q+1], a1);
        a2 = ffma2(w2[q+2], h2[q+2], a2);
        a3 = ffma2(w2[q+3], h2[q+3], a3);
    }
    float acc = bb + (hsum2(a0) + hsum2(a1)) + (hsum2(a2) + hsum2(a3));
    if (lt < 32) g_rawS[a * NINP + lt] = acc;
    else         g_rawD[a * NINP + lt - 32] = acc;
}

// ---------------- 4: BN stats (CTAs 0-63) + scan + zsum zero (CTA 64) -------
__global__ void k_bnstats() {
    int c = blockIdx.x;
    int tid = threadIdx.x;
    if (c == 64) {
        // zero z accumulators (consumed by k_edge, later launch)
        g_zsum[tid] = 0.f; g_zsq[tid] = 0.f;
        // parallel exclusive scan of u-histogram -> start/cursor
        int lane = tid & 31, w = tid >> 5;
        int loc[8]; int s = 0;
        #pragma unroll
        for (int i = 0; i < 8; i++) { loc[i] = s; s += g_cntU[tid * 8 + i]; }
        int vinc = s;
        #pragma unroll
        for (int o = 1; o < 32; o <<= 1) {
            int t2 = __shfl_up_sync(0xffffffffu, vinc, o);
            if (lane >= o) vinc += t2;
        }
        __shared__ int wsum[8];
        if (lane == 31) wsum[w] = vinc;
        __syncthreads();
        if (w == 0 && lane < 8) {
            int x = wsum[lane];
            #pragma unroll
            for (int o = 1; o < 8; o <<= 1) {
                int t2 = __shfl_up_sync(0xffu, x, o);
                if (lane >= o) x += t2;
            }
            wsum[lane] = x;
        }
        __syncthreads();
        int base = (vinc - s) + (w > 0 ? wsum[w - 1] : 0);
        #pragma unroll
        for (int i = 0; i < 8; i++) {
            int st = base + loc[i];
            g_start[tid * 8 + i] = st;
            g_cursor[tid * 8 + i] = st;
        }
        if (tid == 255) g_start[NA] = E_;
        return;
    }
    const float* raw = (c < 32) ? g_rawS : g_rawD;
    const int*   cnt = (c < 32) ? g_cntU : g_cntV;
    int cc = c & 31;
    float s = 0.f, s2 = 0.f;
    for (int a = tid; a < NA; a += 256) {
        float w = (float)cnt[a];
        float x = raw[a * NINP + cc];
        s += w * x; s2 += w * x * x;
    }
    __shared__ float r1[256], r2[256];
    r1[tid] = s; r2[tid] = s2; __syncthreads();
    for (int o = 128; o > 0; o >>= 1) {
        if (tid < o) { r1[tid] += r1[tid + o]; r2[tid] += r2[tid + o]; }
        __syncthreads();
    }
    if (tid == 0) {
        float mu  = r1[0] * (1.0f / E_);
        float var = r2[0] * (1.0f / E_) - mu * mu;
        g_bnMu[c] = mu;
        g_bnInv[c] = rsqrtf(var + 1e-5f);
    }
}

// ---------------- 5: scatter (CTAs 0-255) + bn normalize (CTAs 256-767) -----
__global__ void k_scatnorm(const int* __restrict__ u,
                           const float* __restrict__ gS, const float* __restrict__ beS,
                           const float* __restrict__ gD, const float* __restrict__ beD) {
    int x = blockIdx.x, tid = threadIdx.x;
    if (x < 256) {
        int e = x * 256 + tid;
        int p = atomicAdd(&g_cursor[u[e]], 1);
        g_perm[p] = e;
    } else {
        int t = (x - 256) * 256 + tid;        // 512*256 = 2048*64
        int a = t >> 6, c = t & 63;
        int cc = c & 31;
        if (c < 32) {
            float xv = g_rawS[a * NINP + cc];
            g_hsT[a * NINP + cc] = gS[cc] * (xv - g_bnMu[c]) * g_bnInv[c] + beS[cc];
        } else {
            float xv = g_rawD[a * NINP + cc];
            g_htT[a * NINP + cc] = gD[cc] * (xv - g_bnMu[c]) * g_bnInv[c] + beD[cc];
        }
    }
}

// ---------------- 6: A' GEMM (x<256) + C init (x>=256) ----------------
__global__ void __launch_bounds__(256)
k_agemm(const float* __restrict__ W, const float* __restrict__ V,
        const float* __restrict__ Bb) {
    __shared__ float4 hsr4[16][8];            // 2 KB, used by both branches
    if (blockIdx.x < 256) {
        int rh = blockIdx.x;
        int jj = threadIdx.x & 31, ar = threadIdx.x >> 5;   // ar 0..7
        u64 w2[16];
        #pragma unroll
        for (int k = 0; k < 16; k++) {
            float wl = W[rh * 1024 + (2*k)   * 32 + jj];
            float wh = W[rh * 1024 + (2*k+1) * 32 + jj];
            unsigned lo = __float_as_uint(wl), hi = __float_as_uint(wh);
            w2[k] = ((u64)hi << 32) | lo;
        }
        float v2c = V[rh * 64 + 32 + jj];
        int a0beg = blockIdx.y * (NA / 2);
        for (int a0 = a0beg; a0 < a0beg + NA / 2; a0 += 16) {
            int t = threadIdx.x;
            ((float*)hsr4)[t]       = g_hsT[a0 * NINP + t];
            ((float*)hsr4)[t + 256] = g_hsT[a0 * NINP + t + 256];
            __syncthreads();
            const u64* hA = (const u64*)hsr4[ar];
            const u64* hB = (const u64*)hsr4[ar + 8];
            u64 pa0 = 0, pa1 = 0, pb0 = 0, pb1 = 0;
            #pragma unroll
            for (int k = 0; k < 16; k += 2) {
                pa0 = ffma2(w2[k+0], hA[k+0], pa0);
                pa1 = ffma2(w2[k+1], hA[k+1], pa1);
                pb0 = ffma2(w2[k+0], hB[k+0], pb0);
                pb1 = ffma2(w2[k+1], hB[k+1], pb1);
            }
            g_Ap[(size_t)(a0 + ar)     * 8192 + rh * 32 + jj] = v2c + hsum2(pa0) + hsum2(pa1);
            g_Ap[(size_t)(a0 + ar + 8) * 8192 + rh * 32 + jj] = v2c + hsum2(pb0) + hsum2(pb1);
            __syncthreads();
        }
    } else {
        int unit = (blockIdx.x - 256) + blockIdx.y * 64;    // 0..127
        int a0 = unit * 16;
        int rh = threadIdx.x;
        u64 v1r[16];
        const u64* vp = (const u64*)(V + rh * 64);
        #pragma unroll
        for (int q = 0; q < 16; q++) v1r[q] = vp[q];
        float bb = Bb[rh];
        float* hsm2 = (float*)hsr4;
        hsm2[rh]       = g_hsT[a0 * NINP + rh];
        hsm2[rh + 256] = g_hsT[a0 * NINP + rh + 256];
        __syncthreads();
        #pragma unroll
        for (int i = 0; i < 16; i++) {
            const u64* h2 = (const u64*)(hsm2 + i * 32);
            u64 acc0 = 0, acc1 = 0;
            #pragma unroll
            for (int q = 0; q < 16; q += 2) {
                acc0 = ffma2(v1r[q+0], h2[q+0], acc0);
                acc1 = ffma2(v1r[q+1], h2[q+1], acc1);
            }
            g_C[(a0 + i) * NRH + rh] = bb + hsum2(acc0) + hsum2(acc1);
        }
    }
}

// ---------------- 7: per-edge dot; z[e,rh]; running z-stats -----------------
__global__ void __launch_bounds__(256)
k_edge(const int* __restrict__ v) {
    int a  = blockIdx.x;                      // u-bucket
    int rh = threadIdx.x;
    u64 areg[16];
    const u64* ap = (const u64*)(g_Ap + (size_t)a * 8192 + rh * 32);
    #pragma unroll
    for (int q = 0; q < 16; q++) areg[q] = ap[q];
    float cinit = g_C[a * NRH + rh];
    int s = g_start[a], eend = g_start[a + 1];
    float s1 = 0.f, s2 = 0.f;
    __shared__ float hts[16][32];
    __shared__ int eid[16];
    for (int p0 = s; p0 < eend; p0 += 16) {
        int nb = min(16, eend - p0);
        #pragma unroll
        for (int base = 0; base < 512; base += 256) {
            int flat = base + rh;
            int g = flat >> 5, lj = flat & 31;
            if (g < nb) {
                int e = g_perm[p0 + g];
                if (lj == 0) eid[g] = e;
                hts[g][lj] = g_htT[v[e] * NINP + lj];
            }
        }
        __syncthreads();
        for (int q = 0; q < nb; q++) {
            const u64* hp = (const u64*)hts[q];
            u64 p0a = 0, p1a = 0;
            #pragma unroll
            for (int i = 0; i < 16; i += 2) {
                p0a = ffma2(areg[i+0], hp[i+0], p0a);
                p1a = ffma2(areg[i+1], hp[i+1], p1a);
            }
            float acc = cinit + hsum2(p0a) + hsum2(p1a);
            g_z[(size_t)eid[q] * NRH + rh] = acc;
            s1 += acc; s2 += acc * acc;
        }
        __syncthreads();
    }
    if (eend > s) {
        atomicAdd(&g_zsum[rh], s1);
        atomicAdd(&g_zsq[rh],  s2);
    }
}

// ---------------- 8: warp-per-edge tanh + reduce (zstats fused) -------------
__global__ void __launch_bounds__(256)
k_final(const float* __restrict__ gg, const float* __restrict__ be,
        const float* __restrict__ uu, float* __restrict__ out) {
    __shared__ float ssc[256], sof[256], su[256];
    int tid = threadIdx.x;
    {   // fused z layernorm params (deterministic, recomputed per CTA)
        float mu  = g_zsum[tid] * (1.0f / E_);
        float var = g_zsq[tid] * (1.0f / E_) - mu * mu;
        float sc  = gg[tid] * rsqrtf(var + 1e-5f);
        ssc[tid] = sc;
        sof[tid] = be[tid] - sc * mu;
        su[tid]  = uu[tid];
    }
    __syncthreads();
    int w = tid >> 5, l = tid & 31;
    int rh0 = l * 8;
    float sc0 = ssc[rh0+0], sc1 = ssc[rh0+1], sc2 = ssc[rh0+2], sc3 = ssc[rh0+3];
    float sc4 = ssc[rh0+4], sc5 = ssc[rh0+5], sc6 = ssc[rh0+6], sc7 = ssc[rh0+7];
    float of0 = sof[rh0+0], of1 = sof[rh0+1], of2 = sof[rh0+2], of3 = sof[rh0+3];
    float of4 = sof[rh0+4], of5 = sof[rh0+5], of6 = sof[rh0+6], of7 = sof[rh0+7];
    float u0 = su[rh0+0], u1 = su[rh0+1], u2 = su[rh0+2], u3 = su[rh0+3];
    float u4 = su[rh0+4], u5 = su[rh0+5], u6 = su[rh0+6], u7 = su[rh0+7];
    int e0 = blockIdx.x * 64 + w * 8;
    #pragma unroll
    for (int i = 0; i < 8; i++) {
        int e = e0 + i;
        const float4* zp = (const float4*)(g_z + (size_t)e * NRH) + l * 2;
        float4 za = zp[0], zb = zp[1];
        float s =  u0 * tanha(fmaf(sc0, za.x, of0));
        s += u1 * tanha(fmaf(sc1, za.y, of1));
        s += u2 * tanha(fmaf(sc2, za.z, of2));
        s += u3 * tanha(fmaf(sc3, za.w, of3));
        s += u4 * tanha(fmaf(sc4, zb.x, of4));
        s += u5 * tanha(fmaf(sc5, zb.y, of5));
        s += u6 * tanha(fmaf(sc6, zb.z, of6));
        s += u7 * tanha(fmaf(sc7, zb.w, of7));
        s += __shfl_xor_sync(0xffffffffu, s, 1);
        if ((l & 1) == 0) out[(size_t)e * 16 + (l >> 1)] = s;
    }
}

// ---------------- launch ----------------
extern "C" void kernel_launch(void* const* d_in, const int* in_sizes, int n_in,
                              void* d_out, int out_size) {
    const int*   seq  = (const int*)d_in[0];
    const int*   p2g  = (const int*)d_in[1];
    const int*   idx  = (const int*)d_in[2];
    const int*   u    = (const int*)d_in[3];
    const int*   v    = (const int*)d_in[4];
    const float* emb  = (const float*)d_in[5];
    const float* wihF = (const float*)d_in[6];
    const float* whhF = (const float*)d_in[7];
    const float* bihF = (const float*)d_in[8];
    const float* bhhF = (const float*)d_in[9];
    const float* wihB = (const float*)d_in[10];
    const float* whhB = (const float*)d_in[11];
    const float* bihB = (const float*)d_in[12];
    const float* bhhB = (const float*)d_in[13];
    const float* wS   = (const float*)d_in[14];
    const float* bS   = (const float*)d_in[15];
    const float* wD   = (const float*)d_in[16];
    const float* bD   = (const float*)d_in[17];
    const float* gS   = (const float*)d_in[18];
    const float* beS  = (const float*)d_in[19];
    const float* gD   = (const float*)d_in[20];
    const float* beD  = (const float*)d_in[21];
    const float* ntlW = (const float*)d_in[22];
    const float* ntlV = (const float*)d_in[23];
    const float* ntlB = (const float*)d_in[24];
    const float* ntlU = (const float*)d_in[25];
    const float* ntlG = (const float*)d_in[26];
    const float* ntlBe= (const float*)d_in[27];
    float* out = (float*)d_out;

    k_embed    <<<64, 256>>>(seq, p2g, emb);
    k_lstm     <<<128, 256>>>(wihF, whhF, bihF, bhhF, wihB, whhB, bihB, bhhB);
    k_nodeproj <<<512, 256>>>(p2g, idx, u, v, wS, bS, wD, bD);
    k_bnstats  <<<65, 256>>>();
    k_scatnorm <<<768, 256>>>(u, gS, beS, gD, beD);
    k_agemm    <<<dim3(320, 2), 256>>>(ntlW, ntlV, ntlB);
    k_edge     <<<2048, 256>>>(v);
    k_final    <<<1024, 256>>>(ntlG, ntlBe, ntlU, out);
}